// round 6
// baseline (speedup 1.0000x reference)
#include <cuda_runtime.h>
#include <mma.h>
#include <math.h>
#include <stdint.h>

using namespace nvcuda;

#define AD 1024
#define BD 16384
#define DD 768
#define TEMPC 100.0f
#define EPSC 1e-8f
#define NONDIFF 30
#define DIFFST 10

// ---- device scratch (allocation-free: __device__ globals) ----
__device__ float g_anorm[AD * DD];
__device__ float g_X[AD * AD];
__device__ float g_Xh[AD * AD];
__device__ float g_Xl[AD * AD];
__device__ float g_rsx[AD];
__device__ float g_q[AD * BD];
__device__ float g_c[AD * BD];
__device__ float g_grad[AD * BD];
__device__ float g_sm[AD * BD];
__device__ float g_smT_h[(size_t)BD * AD];   // transposed hi part [n][k]
__device__ float g_smT_l[(size_t)BD * AD];   // transposed lo part [n][k]
__device__ float g_xsm[AD * BD];
__device__ float g_ynorm[BD];
__device__ float g_invyn[BD];
__device__ int   g_amin[AD];
__device__ float g_num[BD];
__device__ float g_denpart[BD / 32];

__device__ __forceinline__ float tf32_hi(float x) {
    float r;
    asm("cvt.rna.tf32.f32 %0, %1;" : "=f"(r) : "f"(x));
    return r;
}
__device__ __forceinline__ uint32_t smem_u32(const void* p) {
    uint32_t a;
    asm("{ .reg .u64 t; cvta.to.shared.u64 t, %1; cvt.u32.u64 %0, t; }" : "=r"(a) : "l"(p));
    return a;
}
#define CP16(dst, src) asm volatile("cp.async.cg.shared.global [%0], [%1], 16;" :: "r"(dst), "l"(src))
#define CP_COMMIT()    asm volatile("cp.async.commit_group;" ::: "memory")
#define CP_WAIT(n)     asm volatile("cp.async.wait_group %0;" :: "n"(n) : "memory")

// =====================================================================
// small init kernels
// =====================================================================
__global__ void ynorm_kernel(const float* __restrict__ y) {
    int w = (blockIdx.x * blockDim.x + threadIdx.x) >> 5;
    int lane = threadIdx.x & 31;
    if (w >= BD) return;
    const float* row = y + (size_t)w * DD;
    float s = 0.f;
    for (int d = lane; d < DD; d += 32) s += fabsf(row[d]);
#pragma unroll
    for (int o = 16; o; o >>= 1) s += __shfl_xor_sync(0xffffffffu, s, o);
    if (!lane) { g_ynorm[w] = s; g_invyn[w] = 1.0f / s; }
}

__global__ void anorm_kernel(const float* __restrict__ atoms) {
    int r = blockIdx.x;
    const float* row = atoms + (size_t)r * DD;
    __shared__ float red[256];
    float s = 0.f;
    for (int d = threadIdx.x; d < DD; d += 256) s += fabsf(row[d]);
    red[threadIdx.x] = s;
    __syncthreads();
    for (int o = 128; o; o >>= 1) {
        if (threadIdx.x < o) red[threadIdx.x] += red[threadIdx.x + o];
        __syncthreads();
    }
    float nrm = red[0];
    for (int d = threadIdx.x; d < DD; d += 256)
        g_anorm[r * DD + d] = row[d] / nrm;
}

__global__ void rowsumX_kernel() {
    int w = (blockIdx.x * blockDim.x + threadIdx.x) >> 5;
    int lane = threadIdx.x & 31;
    if (w >= AD) return;
    float s = 0.f;
    for (int k = lane; k < AD; k += 32) s += g_X[w * AD + k];
#pragma unroll
    for (int o = 16; o; o >>= 1) s += __shfl_xor_sync(0xffffffffu, s, o);
    if (!lane) g_rsx[w] = s;
}

// split X into tf32 hi/lo parts
__global__ void xsplit_kernel() {
    size_t i = ((size_t)blockIdx.x * 256 + threadIdx.x) * 4;
    float4 x = *reinterpret_cast<const float4*>(g_X + i);
    float4 h, l;
    h.x = tf32_hi(x.x); l.x = x.x - h.x;
    h.y = tf32_hi(x.y); l.y = x.y - h.y;
    h.z = tf32_hi(x.z); l.z = x.z - h.z;
    h.w = tf32_hi(x.w); l.w = x.w - h.w;
    *reinterpret_cast<float4*>(g_Xh + i) = h;
    *reinterpret_cast<float4*>(g_Xl + i) = l;
}

__global__ void init_kernel() {
    size_t i4 = ((size_t)blockIdx.x * 256 + threadIdx.x) * 4;
    int a = (int)(i4 / BD);
    float rs = g_rsx[a] * (1.0f / AD);
    float4 q4 = *reinterpret_cast<const float4*>(g_q + i4);
    float4 g;
    g.x = rs - q4.x; g.y = rs - q4.y; g.z = rs - q4.z; g.w = rs - q4.w;
    *reinterpret_cast<float4*>(g_grad + i4) = g;
    float4 cc = make_float4(1.0f / AD, 1.0f / AD, 1.0f / AD, 1.0f / AD);
    *reinterpret_cast<float4*>(g_c + i4) = cc;
}

// =====================================================================
// fp32 SIMT GEMM (used for X, q, recon)
// =====================================================================
template <bool AKM, bool BKM, int SCALE>
__global__ void __launch_bounds__(256) gemm_kernel(
    const float* __restrict__ A, const float* __restrict__ B, float* __restrict__ C,
    int M, int N, int K, int lda, int ldb, int ldc, const float* __restrict__ scale)
{
    __shared__ float As[16][132];
    __shared__ float Bs[16][132];
    const int tid = threadIdx.x;
    const int tx = tid & 15, ty = tid >> 4;
    const int m0 = blockIdx.y * 128, n0 = blockIdx.x * 128;
    float acc[8][8];
#pragma unroll
    for (int i = 0; i < 8; i++)
#pragma unroll
        for (int j = 0; j < 8; j++) acc[i][j] = 0.f;

    for (int k0 = 0; k0 < K; k0 += 16) {
#pragma unroll
        for (int i = 0; i < 2; i++) {
            int lin = tid + i * 256;
            if (AKM) {
                int kk = lin >> 5, mm = (lin & 31) << 2;
                float4 v = *reinterpret_cast<const float4*>(A + (size_t)(k0 + kk) * lda + (m0 + mm));
                *reinterpret_cast<float4*>(&As[kk][mm]) = v;
            } else {
                int mm = lin >> 2, kk = (lin & 3) << 2;
                float4 v = *reinterpret_cast<const float4*>(A + (size_t)(m0 + mm) * lda + (k0 + kk));
                As[kk + 0][mm] = v.x; As[kk + 1][mm] = v.y;
                As[kk + 2][mm] = v.z; As[kk + 3][mm] = v.w;
            }
        }
#pragma unroll
        for (int i = 0; i < 2; i++) {
            int lin = tid + i * 256;
            if (BKM) {
                int kk = lin >> 5, nn = (lin & 31) << 2;
                float4 v = *reinterpret_cast<const float4*>(B + (size_t)(k0 + kk) * ldb + (n0 + nn));
                *reinterpret_cast<float4*>(&Bs[kk][nn]) = v;
            } else {
                int nn = lin >> 2, kk = (lin & 3) << 2;
                float4 v = *reinterpret_cast<const float4*>(B + (size_t)(n0 + nn) * ldb + (k0 + kk));
                Bs[kk + 0][nn] = v.x; Bs[kk + 1][nn] = v.y;
                Bs[kk + 2][nn] = v.z; Bs[kk + 3][nn] = v.w;
            }
        }
        __syncthreads();
#pragma unroll
        for (int k = 0; k < 16; k++) {
            float af[8], bf[8];
            *reinterpret_cast<float4*>(&af[0]) = *reinterpret_cast<float4*>(&As[k][ty * 8]);
            *reinterpret_cast<float4*>(&af[4]) = *reinterpret_cast<float4*>(&As[k][ty * 8 + 4]);
            *reinterpret_cast<float4*>(&bf[0]) = *reinterpret_cast<float4*>(&Bs[k][tx * 8]);
            *reinterpret_cast<float4*>(&bf[4]) = *reinterpret_cast<float4*>(&Bs[k][tx * 8 + 4]);
#pragma unroll
            for (int i = 0; i < 8; i++)
#pragma unroll
                for (int j = 0; j < 8; j++) acc[i][j] += af[i] * bf[j];
        }
        __syncthreads();
    }
#pragma unroll
    for (int i = 0; i < 8; i++) {
        int m = m0 + ty * 8 + i;
        float rowf = (SCALE == 2) ? scale[m] : 1.f;
#pragma unroll
        for (int j = 0; j < 8; j++) {
            float f = (SCALE == 1) ? scale[n0 + tx * 8 + j] : rowf;
            C[(size_t)m * ldc + n0 + tx * 8 + j] = acc[i][j] * f;
        }
    }
}

// =====================================================================
// xsm = X @ sm via wmma tf32 (3xTF32 split), cp.async double-buffered.
// A = Xh/Xl [M=1024, K=1024] row-major; B = smT_h/l [N=16384, K=1024]
// (= B col-major). CTA tile 128x128, 8 warps (4m x 2n), warp tile 32x64.
// =====================================================================
#define LDS_PAD 36
#define ARR_B   (128 * LDS_PAD * 4)        // 18432 bytes per array
#define BUF_B   (4 * ARR_B)                // AH, AL, BH, BL
#define SMEM_DYN (2 * BUF_B)               // 147456 bytes

__global__ void __launch_bounds__(256, 1) xsm_wmma_kernel() {
    extern __shared__ float smf[];
    const uint32_t sb = smem_u32(smf);
    const int tid = threadIdx.x;
    const int wid = tid >> 5;
    const int m0 = blockIdx.y * 128;
    const int n0 = blockIdx.x * 128;
    const int wm = (wid >> 1) * 32;        // warp m offset 0/32/64/96
    const int wn = (wid & 1) * 64;         // warp n offset 0/64

    const float* srcs[4];
    srcs[0] = g_Xh    + (size_t)m0 * AD;
    srcs[1] = g_Xl    + (size_t)m0 * AD;
    srcs[2] = g_smT_h + (size_t)n0 * AD;
    srcs[3] = g_smT_l + (size_t)n0 * AD;

    wmma::fragment<wmma::accumulator, 16, 16, 8, float> acc[2][4];
#pragma unroll
    for (int i = 0; i < 2; i++)
#pragma unroll
        for (int j = 0; j < 4; j++) wmma::fill_fragment(acc[i][j], 0.0f);

#define PREFETCH(CK, BUF) do { \
    const int _k0 = (CK) * 32; \
    _Pragma("unroll") \
    for (int arr = 0; arr < 4; arr++) { \
        _Pragma("unroll") \
        for (int s = 0; s < 4; s++) { \
            int seg = tid + s * 256; \
            int row = seg >> 3, sg = seg & 7; \
            uint32_t dst = sb + (BUF) * BUF_B + arr * ARR_B + (uint32_t)(row * LDS_PAD + sg * 4) * 4; \
            CP16(dst, srcs[arr] + (size_t)row * AD + _k0 + sg * 4); \
        } \
    } \
    CP_COMMIT(); } while (0)

    PREFETCH(0, 0);

    const int NCK = AD / 32;               // 32 chunks
    for (int ck = 0; ck < NCK; ck++) {
        const int buf = ck & 1;
        if (ck + 1 < NCK) {
            PREFETCH(ck + 1, (ck + 1) & 1);
            CP_WAIT(1);
        } else {
            CP_WAIT(0);
        }
        __syncthreads();

        const float* Ah = smf + (buf * BUF_B + 0 * ARR_B) / 4;
        const float* Al = smf + (buf * BUF_B + 1 * ARR_B) / 4;
        const float* Bh = smf + (buf * BUF_B + 2 * ARR_B) / 4;
        const float* Bl = smf + (buf * BUF_B + 3 * ARR_B) / 4;

#pragma unroll
        for (int ks = 0; ks < 4; ks++) {
            wmma::fragment<wmma::matrix_a, 16, 16, 8, wmma::precision::tf32, wmma::row_major> ah[2], al[2];
            wmma::fragment<wmma::matrix_b, 16, 16, 8, wmma::precision::tf32, wmma::col_major> bh[4], bl[4];
#pragma unroll
            for (int i = 0; i < 2; i++) {
                wmma::load_matrix_sync(ah[i], Ah + (wm + i * 16) * LDS_PAD + ks * 8, LDS_PAD);
                wmma::load_matrix_sync(al[i], Al + (wm + i * 16) * LDS_PAD + ks * 8, LDS_PAD);
            }
#pragma unroll
            for (int j = 0; j < 4; j++) {
                wmma::load_matrix_sync(bh[j], Bh + (wn + j * 16) * LDS_PAD + ks * 8, LDS_PAD);
                wmma::load_matrix_sync(bl[j], Bl + (wn + j * 16) * LDS_PAD + ks * 8, LDS_PAD);
            }
#pragma unroll
            for (int i = 0; i < 2; i++)
#pragma unroll
                for (int j = 0; j < 4; j++) {
                    wmma::mma_sync(acc[i][j], ah[i], bh[j], acc[i][j]);
                    wmma::mma_sync(acc[i][j], ah[i], bl[j], acc[i][j]);
                    wmma::mma_sync(acc[i][j], al[i], bh[j], acc[i][j]);
                }
        }
        __syncthreads();
    }
#undef PREFETCH

#pragma unroll
    for (int i = 0; i < 2; i++)
#pragma unroll
        for (int j = 0; j < 4; j++) {
            float* dst = g_xsm + (size_t)(m0 + wm + i * 16) * BD + (n0 + wn + j * 16);
            wmma::store_matrix_sync(dst, acc[i][j], BD, wmma::mem_row_major);
        }
}

// =====================================================================
// argmin over batch per atom row
// =====================================================================
__global__ void argmin_kernel() {
    int a = blockIdx.x;
    const float* row = g_grad + (size_t)a * BD;
    float bv = INFINITY; int bi = 0;
    for (int j = threadIdx.x; j < BD; j += 256) {
        float v = row[j];
        if (v < bv) { bv = v; bi = j; }
    }
    __shared__ float sv[256];
    __shared__ int   si[256];
    sv[threadIdx.x] = bv; si[threadIdx.x] = bi;
    __syncthreads();
    for (int o = 128; o; o >>= 1) {
        if (threadIdx.x < o) {
            float v2 = sv[threadIdx.x + o]; int i2 = si[threadIdx.x + o];
            if (v2 < sv[threadIdx.x] ||
                (v2 == sv[threadIdx.x] && i2 < si[threadIdx.x])) {
                sv[threadIdx.x] = v2; si[threadIdx.x] = i2;
            }
        }
        __syncthreads();
    }
    if (!threadIdx.x) g_amin[a] = si[0];
}

__device__ __forceinline__ void build_sel_list(
    const int* amin_s, int j0, int* sel_a, int* sel_j, int* nsel_s,
    int tid, int tx)
{
    if (tid < 32) {
        int cnt = 0;
        for (int base = 0; base < AD; base += 32) {
            int a = base + tx;
            int jm = amin_s[a];
            bool mt = (jm >= j0 && jm < j0 + 32);
            unsigned mask = __ballot_sync(0xffffffffu, mt);
            if (mt) {
                int p = cnt + __popc(mask & ((1u << tx) - 1u));
                sel_a[p] = a; sel_j[p] = jm;
            }
            cnt += __popc(mask);
        }
        if (tx == 0) *nsel_s = cnt;
    }
}

__global__ void __launch_bounds__(256) nd_reduce_kernel() {
    const int tx = threadIdx.x, ty = threadIdx.y, tid = ty * 32 + tx;
    const int j0 = blockIdx.x * 32, j = j0 + tx;
    __shared__ int amin_s[AD];
    __shared__ int sel_a[AD], sel_j[AD], nsel_s;
    for (int a = tid; a < AD; a += 256) amin_s[a] = g_amin[a];
    __syncthreads();
    build_sel_list(amin_s, j0, sel_a, sel_j, &nsel_s, tid, tx);
    __syncthreads();
    const int ns = nsel_s;

    float num = 0.f, den = 0.f;
    for (int a = ty; a < AD; a += 8) {
        size_t idx = (size_t)a * BD + j;
        float cc = g_c[idx], gg = g_grad[idx], qq = g_q[idx];
        float S = 0.f;
        for (int e = 0; e < ns; e++)
            if (sel_j[e] == j) S += g_X[a * AD + sel_a[e]];
        float am = (amin_s[a] == j) ? 1.f : 0.f;
        float dd = am - cc;
        num += dd * gg;
        den += dd * (S - gg - qq);
    }
    __shared__ float rn[8][33], rd[8][33], colden[32];
    rn[ty][tx] = num; rd[ty][tx] = den;
    __syncthreads();
    if (ty == 0) {
        float n2 = 0.f, d2 = 0.f;
        for (int t = 0; t < 8; t++) { n2 += rn[t][tx]; d2 += rd[t][tx]; }
        g_num[j] = n2; colden[tx] = d2;
    }
    __syncthreads();
    if (tid == 0) {
        float d3 = 0.f;
        for (int t = 0; t < 32; t++) d3 += colden[t];
        g_denpart[blockIdx.x] = d3;
    }
}

__global__ void __launch_bounds__(256) nd_update_kernel() {
    const int tx = threadIdx.x, ty = threadIdx.y, tid = ty * 32 + tx;
    const int j0 = blockIdx.x * 32, j = j0 + tx;
    __shared__ float red[256];
    __shared__ int amin_s[AD];
    __shared__ int sel_a[AD], sel_j[AD], nsel_s;
    red[tid] = g_denpart[tid] + g_denpart[tid + 256];
    for (int a = tid; a < AD; a += 256) amin_s[a] = g_amin[a];
    __syncthreads();
    for (int o = 128; o; o >>= 1) {
        if (tid < o) red[tid] += red[tid + o];
        __syncthreads();
    }
    build_sel_list(amin_s, j0, sel_a, sel_j, &nsel_s, tid, tx);
    __syncthreads();
    const int ns = nsel_s;
    const float denom = red[0] + EPSC;
    const float lam = fminf(fmaxf(-g_num[j] / denom, 0.f), 1.f);

    for (int a = ty; a < AD; a += 8) {
        size_t idx = (size_t)a * BD + j;
        float cc = g_c[idx], gg = g_grad[idx], qq = g_q[idx];
        float S = 0.f;
        for (int e = 0; e < ns; e++)
            if (sel_j[e] == j) S += g_X[a * AD + sel_a[e]];
        float am = (amin_s[a] == j) ? 1.f : 0.f;
        float dd = am - cc;
        float xd = S - gg - qq;
        g_c[idx]   = cc + lam * dd;
        g_grad[idx] = gg + lam * xd;
    }
}

// =====================================================================
// softmax: writes normal-layout g_sm AND transposed tf32 hi/lo operands
// =====================================================================
__global__ void __launch_bounds__(256) softmaxT_kernel() {
    const int tx = threadIdx.x, ty = threadIdx.y;
    const int j0 = blockIdx.x * 32, j = j0 + tx;
    float m = -INFINITY, s = 0.f;
    for (int a = ty; a < AD; a += 8) {
        float v = -TEMPC * g_grad[(size_t)a * BD + j];
        if (v > m) { s = s * expf(m - v) + 1.f; m = v; }
        else        s += expf(v - m);
    }
    __shared__ float mm[8][33], ss[8][33], fm[32], fs[32];
    mm[ty][tx] = m; ss[ty][tx] = s;
    __syncthreads();
    if (ty == 0) {
        float M = mm[0][tx], S = ss[0][tx];
        for (int t = 1; t < 8; t++) {
            float m2 = mm[t][tx], s2 = ss[t][tx];
            float Mn = fmaxf(M, m2);
            S = S * expf(M - Mn) + s2 * expf(m2 - Mn);
            M = Mn;
        }
        fm[tx] = M; fs[tx] = S;
    }
    __syncthreads();
    const float M = fm[tx];
    const float invS = 1.0f / fs[tx];

    __shared__ float th[32][33], tl[32][33];
    for (int at = 0; at < 32; at++) {
        const int a0 = at * 32;
        for (int aa = ty; aa < 32; aa += 8) {
            size_t idx = (size_t)(a0 + aa) * BD + j;
            float v = -TEMPC * g_grad[idx];
            float e = expf(v - M) * invS;
            g_sm[idx] = e;
            float hi = tf32_hi(e);
            th[aa][tx] = hi;
            tl[aa][tx] = e - hi;
        }
        __syncthreads();
#pragma unroll
        for (int rr = 0; rr < 4; rr++) {
            int r = ty * 4 + rr;
            g_smT_h[(size_t)(j0 + r) * AD + a0 + tx] = th[tx][r];
            g_smT_l[(size_t)(j0 + r) * AD + a0 + tx] = tl[tx][r];
        }
        __syncthreads();
    }
}

__global__ void __launch_bounds__(256) d_reduce_kernel() {
    const int tx = threadIdx.x, ty = threadIdx.y, tid = ty * 32 + tx;
    const int j = blockIdx.x * 32 + tx;
    float num = 0.f, den = 0.f;
    for (int a = ty; a < AD; a += 8) {
        size_t idx = (size_t)a * BD + j;
        float dd = g_sm[idx] - g_c[idx];
        float xd = g_xsm[idx] - g_grad[idx] - g_q[idx];
        num += dd * g_grad[idx];
        den += dd * xd;
    }
    __shared__ float rn[8][33], rd[8][33], colden[32];
    rn[ty][tx] = num; rd[ty][tx] = den;
    __syncthreads();
    if (ty == 0) {
        float n2 = 0.f, d2 = 0.f;
        for (int t = 0; t < 8; t++) { n2 += rn[t][tx]; d2 += rd[t][tx]; }
        g_num[j] = n2; colden[tx] = d2;
    }
    __syncthreads();
    if (tid == 0) {
        float d3 = 0.f;
        for (int t = 0; t < 32; t++) d3 += colden[t];
        g_denpart[blockIdx.x] = d3;
    }
}

__global__ void __launch_bounds__(256) d_update_kernel() {
    const int tx = threadIdx.x, ty = threadIdx.y, tid = ty * 32 + tx;
    const int j = blockIdx.x * 32 + tx;
    __shared__ float red[256];
    red[tid] = g_denpart[tid] + g_denpart[tid + 256];
    __syncthreads();
    for (int o = 128; o; o >>= 1) {
        if (tid < o) red[tid] += red[tid + o];
        __syncthreads();
    }
    const float denom = red[0] + EPSC;
    const float lam = fminf(fmaxf(-g_num[j] / denom, 0.f), 1.f);
    for (int a = ty; a < AD; a += 8) {
        size_t idx = (size_t)a * BD + j;
        float cc = g_c[idx], gg = g_grad[idx];
        float dd = g_sm[idx] - cc;
        float xd = g_xsm[idx] - gg - g_q[idx];
        g_c[idx]   = cc + lam * dd;
        g_grad[idx] = gg + lam * xd;
    }
}

// =====================================================================
// host launcher
// =====================================================================
extern "C" void kernel_launch(void* const* d_in, const int* in_sizes, int n_in,
                              void* d_out, int out_size)
{
    const float* y     = (const float*)d_in[0];
    const float* atoms = (const float*)d_in[1];
    float* out = (float*)d_out;

    float *p_anorm, *p_X, *p_q, *p_c, *p_invyn, *p_ynorm;
    cudaGetSymbolAddress((void**)&p_anorm, g_anorm);
    cudaGetSymbolAddress((void**)&p_X,     g_X);
    cudaGetSymbolAddress((void**)&p_q,     g_q);
    cudaGetSymbolAddress((void**)&p_c,     g_c);
    cudaGetSymbolAddress((void**)&p_invyn, g_invyn);
    cudaGetSymbolAddress((void**)&p_ynorm, g_ynorm);

    cudaFuncSetAttribute(xsm_wmma_kernel,
                         cudaFuncAttributeMaxDynamicSharedMemorySize, SMEM_DYN);

    ynorm_kernel<<<BD / 8, 256>>>(y);
    anorm_kernel<<<AD, 256>>>(atoms);

    gemm_kernel<false, false, 0><<<dim3(AD / 128, AD / 128), 256>>>(
        p_anorm, p_anorm, p_X, AD, AD, DD, DD, DD, AD, nullptr);
    rowsumX_kernel<<<AD / 8, 256>>>();
    xsplit_kernel<<<(AD * AD) / 1024, 256>>>();

    gemm_kernel<false, false, 1><<<dim3(BD / 128, AD / 128), 256>>>(
        p_anorm, y, p_q, AD, BD, DD, DD, DD, BD, p_invyn);

    init_kernel<<<(AD * BD) / 1024, 256>>>();

    for (int s = 0; s < NONDIFF; s++) {
        argmin_kernel<<<AD, 256>>>();
        nd_reduce_kernel<<<BD / 32, dim3(32, 8)>>>();
        nd_update_kernel<<<BD / 32, dim3(32, 8)>>>();
    }

    for (int s = 0; s < DIFFST; s++) {
        softmaxT_kernel<<<BD / 32, dim3(32, 8)>>>();
        xsm_wmma_kernel<<<dim3(BD / 128, AD / 128), 256, SMEM_DYN>>>();
        d_reduce_kernel<<<BD / 32, dim3(32, 8)>>>();
        d_update_kernel<<<BD / 32, dim3(32, 8)>>>();
    }

    gemm_kernel<true, true, 2><<<dim3(DD / 128, BD / 128), 256>>>(
        p_c, p_anorm, out, BD, DD, AD, BD, DD, DD, p_ynorm);
}

// round 7
// speedup vs baseline: 1.4169x; 1.4169x over previous
#include <cuda_runtime.h>
#include <mma.h>
#include <math.h>
#include <stdint.h>

using namespace nvcuda;

#define AD 1024
#define BD 16384
#define DD 768
#define TEMPC 100.0f
#define EPSC 1e-8f
#define NONDIFF 30
#define DIFFST 10

// ---- device scratch (allocation-free: __device__ globals) ----
__device__ float g_anorm[AD * DD];
__device__ float g_X[AD * AD];
__device__ float g_Xh[AD * AD];          // rna-tf32 rounded X
__device__ float g_rsx[AD];
__device__ float g_q[AD * BD];
__device__ float g_c[AD * BD];
__device__ float g_grad[AD * BD];
__device__ float g_sm[AD * BD];
__device__ float g_smT_h[(size_t)BD * AD];   // transposed rna-tf32 softmax [n][k]
__device__ float g_xsm[AD * BD];
__device__ float g_ynorm[BD];
__device__ float g_invyn[BD];
__device__ int   g_amin[AD];
__device__ float g_num[BD];
__device__ float g_denpart[BD / 32];

__device__ __forceinline__ float tf32_rna(float x) {
    float r;
    asm("cvt.rna.tf32.f32 %0, %1;" : "=f"(r) : "f"(x));
    return r;
}
__device__ __forceinline__ uint32_t smem_u32(const void* p) {
    uint32_t a;
    asm("{ .reg .u64 t; cvta.to.shared.u64 t, %1; cvt.u32.u64 %0, t; }" : "=r"(a) : "l"(p));
    return a;
}
#define CP16(dst, src) asm volatile("cp.async.cg.shared.global [%0], [%1], 16;" :: "r"(dst), "l"(src))
#define CP_COMMIT()    asm volatile("cp.async.commit_group;" ::: "memory")
#define CP_WAIT(n)     asm volatile("cp.async.wait_group %0;" :: "n"(n) : "memory")

// =====================================================================
// small init kernels
// =====================================================================
__global__ void ynorm_kernel(const float* __restrict__ y) {
    int w = (blockIdx.x * blockDim.x + threadIdx.x) >> 5;
    int lane = threadIdx.x & 31;
    if (w >= BD) return;
    const float* row = y + (size_t)w * DD;
    float s = 0.f;
    for (int d = lane; d < DD; d += 32) s += fabsf(row[d]);
#pragma unroll
    for (int o = 16; o; o >>= 1) s += __shfl_xor_sync(0xffffffffu, s, o);
    if (!lane) { g_ynorm[w] = s; g_invyn[w] = 1.0f / s; }
}

__global__ void anorm_kernel(const float* __restrict__ atoms) {
    int r = blockIdx.x;
    const float* row = atoms + (size_t)r * DD;
    __shared__ float red[256];
    float s = 0.f;
    for (int d = threadIdx.x; d < DD; d += 256) s += fabsf(row[d]);
    red[threadIdx.x] = s;
    __syncthreads();
    for (int o = 128; o; o >>= 1) {
        if (threadIdx.x < o) red[threadIdx.x] += red[threadIdx.x + o];
        __syncthreads();
    }
    float nrm = red[0];
    for (int d = threadIdx.x; d < DD; d += 256)
        g_anorm[r * DD + d] = row[d] / nrm;
}

__global__ void rowsumX_kernel() {
    int w = (blockIdx.x * blockDim.x + threadIdx.x) >> 5;
    int lane = threadIdx.x & 31;
    if (w >= AD) return;
    float s = 0.f;
    for (int k = lane; k < AD; k += 32) s += g_X[w * AD + k];
#pragma unroll
    for (int o = 16; o; o >>= 1) s += __shfl_xor_sync(0xffffffffu, s, o);
    if (!lane) g_rsx[w] = s;
}

// round X to tf32 (rna) for the tensor-core GEMM operand
__global__ void xsplit_kernel() {
    size_t i = ((size_t)blockIdx.x * 256 + threadIdx.x) * 4;
    float4 x = *reinterpret_cast<const float4*>(g_X + i);
    float4 h;
    h.x = tf32_rna(x.x); h.y = tf32_rna(x.y);
    h.z = tf32_rna(x.z); h.w = tf32_rna(x.w);
    *reinterpret_cast<float4*>(g_Xh + i) = h;
}

__global__ void init_kernel() {
    size_t i4 = ((size_t)blockIdx.x * 256 + threadIdx.x) * 4;
    int a = (int)(i4 / BD);
    float rs = g_rsx[a] * (1.0f / AD);
    float4 q4 = *reinterpret_cast<const float4*>(g_q + i4);
    float4 g;
    g.x = rs - q4.x; g.y = rs - q4.y; g.z = rs - q4.z; g.w = rs - q4.w;
    *reinterpret_cast<float4*>(g_grad + i4) = g;
    float4 cc = make_float4(1.0f / AD, 1.0f / AD, 1.0f / AD, 1.0f / AD);
    *reinterpret_cast<float4*>(g_c + i4) = cc;
}

// =====================================================================
// fp32 SIMT GEMM (used for X, q, recon — full fp32 precision)
// =====================================================================
template <bool AKM, bool BKM, int SCALE>
__global__ void __launch_bounds__(256) gemm_kernel(
    const float* __restrict__ A, const float* __restrict__ B, float* __restrict__ C,
    int M, int N, int K, int lda, int ldb, int ldc, const float* __restrict__ scale)
{
    __shared__ float As[16][132];
    __shared__ float Bs[16][132];
    const int tid = threadIdx.x;
    const int tx = tid & 15, ty = tid >> 4;
    const int m0 = blockIdx.y * 128, n0 = blockIdx.x * 128;
    float acc[8][8];
#pragma unroll
    for (int i = 0; i < 8; i++)
#pragma unroll
        for (int j = 0; j < 8; j++) acc[i][j] = 0.f;

    for (int k0 = 0; k0 < K; k0 += 16) {
#pragma unroll
        for (int i = 0; i < 2; i++) {
            int lin = tid + i * 256;
            if (AKM) {
                int kk = lin >> 5, mm = (lin & 31) << 2;
                float4 v = *reinterpret_cast<const float4*>(A + (size_t)(k0 + kk) * lda + (m0 + mm));
                *reinterpret_cast<float4*>(&As[kk][mm]) = v;
            } else {
                int mm = lin >> 2, kk = (lin & 3) << 2;
                float4 v = *reinterpret_cast<const float4*>(A + (size_t)(m0 + mm) * lda + (k0 + kk));
                As[kk + 0][mm] = v.x; As[kk + 1][mm] = v.y;
                As[kk + 2][mm] = v.z; As[kk + 3][mm] = v.w;
            }
        }
#pragma unroll
        for (int i = 0; i < 2; i++) {
            int lin = tid + i * 256;
            if (BKM) {
                int kk = lin >> 5, nn = (lin & 31) << 2;
                float4 v = *reinterpret_cast<const float4*>(B + (size_t)(k0 + kk) * ldb + (n0 + nn));
                *reinterpret_cast<float4*>(&Bs[kk][nn]) = v;
            } else {
                int nn = lin >> 2, kk = (lin & 3) << 2;
                float4 v = *reinterpret_cast<const float4*>(B + (size_t)(n0 + nn) * ldb + (k0 + kk));
                Bs[kk + 0][nn] = v.x; Bs[kk + 1][nn] = v.y;
                Bs[kk + 2][nn] = v.z; Bs[kk + 3][nn] = v.w;
            }
        }
        __syncthreads();
#pragma unroll
        for (int k = 0; k < 16; k++) {
            float af[8], bf[8];
            *reinterpret_cast<float4*>(&af[0]) = *reinterpret_cast<float4*>(&As[k][ty * 8]);
            *reinterpret_cast<float4*>(&af[4]) = *reinterpret_cast<float4*>(&As[k][ty * 8 + 4]);
            *reinterpret_cast<float4*>(&bf[0]) = *reinterpret_cast<float4*>(&Bs[k][tx * 8]);
            *reinterpret_cast<float4*>(&bf[4]) = *reinterpret_cast<float4*>(&Bs[k][tx * 8 + 4]);
#pragma unroll
            for (int i = 0; i < 8; i++)
#pragma unroll
                for (int j = 0; j < 8; j++) acc[i][j] += af[i] * bf[j];
        }
        __syncthreads();
    }
#pragma unroll
    for (int i = 0; i < 8; i++) {
        int m = m0 + ty * 8 + i;
        float rowf = (SCALE == 2) ? scale[m] : 1.f;
#pragma unroll
        for (int j = 0; j < 8; j++) {
            float f = (SCALE == 1) ? scale[n0 + tx * 8 + j] : rowf;
            C[(size_t)m * ldc + n0 + tx * 8 + j] = acc[i][j] * f;
        }
    }
}

// =====================================================================
// xsm = Xh @ smT_h^T : single-pass tf32 wmma, double-buffered cp.async.
// A = Xh [M=1024, K=1024] row-major; B = smT_h [N=16384, K=1024]
// (= B col-major, (k,n) at n*ld + k). CTA 128x128, 8 warps (4m x 2n).
// =====================================================================
#define LDS_PAD 36
#define ARR_B   (128 * LDS_PAD * 4)        // 18432 bytes per array
#define BUF_B   (2 * ARR_B)                // A, B
#define SMEM_DYN (2 * BUF_B)               // 73728 bytes

__global__ void __launch_bounds__(256, 2) xsm_wmma_kernel() {
    extern __shared__ float smf[];
    const uint32_t sb = smem_u32(smf);
    const int tid = threadIdx.x;
    const int wid = tid >> 5;
    const int m0 = blockIdx.y * 128;
    const int n0 = blockIdx.x * 128;
    const int wm = (wid >> 1) * 32;        // warp m offset 0/32/64/96
    const int wn = (wid & 1) * 64;         // warp n offset 0/64

    const float* srcA = g_Xh    + (size_t)m0 * AD;
    const float* srcB = g_smT_h + (size_t)n0 * AD;

    wmma::fragment<wmma::accumulator, 16, 16, 8, float> acc[2][4];
#pragma unroll
    for (int i = 0; i < 2; i++)
#pragma unroll
        for (int j = 0; j < 4; j++) wmma::fill_fragment(acc[i][j], 0.0f);

#define PREFETCH(CK, BUF) do { \
    const int _k0 = (CK) * 32; \
    _Pragma("unroll") \
    for (int s = 0; s < 4; s++) { \
        int seg = tid + s * 256; \
        int row = seg >> 3, sg = seg & 7; \
        uint32_t off = (uint32_t)(row * LDS_PAD + sg * 4) * 4; \
        CP16(sb + (BUF) * BUF_B + off,         srcA + (size_t)row * AD + _k0 + sg * 4); \
        CP16(sb + (BUF) * BUF_B + ARR_B + off, srcB + (size_t)row * AD + _k0 + sg * 4); \
    } \
    CP_COMMIT(); } while (0)

    PREFETCH(0, 0);

    const int NCK = AD / 32;               // 32 chunks
    for (int ck = 0; ck < NCK; ck++) {
        const int buf = ck & 1;
        if (ck + 1 < NCK) {
            PREFETCH(ck + 1, (ck + 1) & 1);
            CP_WAIT(1);
        } else {
            CP_WAIT(0);
        }
        __syncthreads();

        const float* At = smf + (buf * BUF_B) / 4;
        const float* Bt = smf + (buf * BUF_B + ARR_B) / 4;

#pragma unroll
        for (int ks = 0; ks < 4; ks++) {
            wmma::fragment<wmma::matrix_a, 16, 16, 8, wmma::precision::tf32, wmma::row_major> af[2];
            wmma::fragment<wmma::matrix_b, 16, 16, 8, wmma::precision::tf32, wmma::col_major> bf[4];
#pragma unroll
            for (int i = 0; i < 2; i++)
                wmma::load_matrix_sync(af[i], At + (wm + i * 16) * LDS_PAD + ks * 8, LDS_PAD);
#pragma unroll
            for (int j = 0; j < 4; j++)
                wmma::load_matrix_sync(bf[j], Bt + (wn + j * 16) * LDS_PAD + ks * 8, LDS_PAD);
#pragma unroll
            for (int i = 0; i < 2; i++)
#pragma unroll
                for (int j = 0; j < 4; j++)
                    wmma::mma_sync(acc[i][j], af[i], bf[j], acc[i][j]);
        }
        __syncthreads();
    }
#undef PREFETCH

#pragma unroll
    for (int i = 0; i < 2; i++)
#pragma unroll
        for (int j = 0; j < 4; j++) {
            float* dst = g_xsm + (size_t)(m0 + wm + i * 16) * BD + (n0 + wn + j * 16);
            wmma::store_matrix_sync(dst, acc[i][j], BD, wmma::mem_row_major);
        }
}

// =====================================================================
// argmin over batch per atom row
// =====================================================================
__global__ void argmin_kernel() {
    int a = blockIdx.x;
    const float* row = g_grad + (size_t)a * BD;
    float bv = INFINITY; int bi = 0;
    for (int j = threadIdx.x; j < BD; j += 256) {
        float v = row[j];
        if (v < bv) { bv = v; bi = j; }
    }
    __shared__ float sv[256];
    __shared__ int   si[256];
    sv[threadIdx.x] = bv; si[threadIdx.x] = bi;
    __syncthreads();
    for (int o = 128; o; o >>= 1) {
        if (threadIdx.x < o) {
            float v2 = sv[threadIdx.x + o]; int i2 = si[threadIdx.x + o];
            if (v2 < sv[threadIdx.x] ||
                (v2 == sv[threadIdx.x] && i2 < si[threadIdx.x])) {
                sv[threadIdx.x] = v2; si[threadIdx.x] = i2;
            }
        }
        __syncthreads();
    }
    if (!threadIdx.x) g_amin[a] = si[0];
}

__device__ __forceinline__ void build_sel_list(
    const int* amin_s, int j0, int* sel_a, int* sel_j, int* nsel_s,
    int tid, int tx)
{
    if (tid < 32) {
        int cnt = 0;
        for (int base = 0; base < AD; base += 32) {
            int a = base + tx;
            int jm = amin_s[a];
            bool mt = (jm >= j0 && jm < j0 + 32);
            unsigned mask = __ballot_sync(0xffffffffu, mt);
            if (mt) {
                int p = cnt + __popc(mask & ((1u << tx) - 1u));
                sel_a[p] = a; sel_j[p] = jm;
            }
            cnt += __popc(mask);
        }
        if (tx == 0) *nsel_s = cnt;
    }
}

__global__ void __launch_bounds__(256) nd_reduce_kernel() {
    const int tx = threadIdx.x, ty = threadIdx.y, tid = ty * 32 + tx;
    const int j0 = blockIdx.x * 32, j = j0 + tx;
    __shared__ int amin_s[AD];
    __shared__ int sel_a[AD], sel_j[AD], nsel_s;
    for (int a = tid; a < AD; a += 256) amin_s[a] = g_amin[a];
    __syncthreads();
    build_sel_list(amin_s, j0, sel_a, sel_j, &nsel_s, tid, tx);
    __syncthreads();
    const int ns = nsel_s;

    float num = 0.f, den = 0.f;
    for (int a = ty; a < AD; a += 8) {
        size_t idx = (size_t)a * BD + j;
        float cc = g_c[idx], gg = g_grad[idx], qq = g_q[idx];
        float S = 0.f;
        for (int e = 0; e < ns; e++)
            if (sel_j[e] == j) S += g_X[a * AD + sel_a[e]];
        float am = (amin_s[a] == j) ? 1.f : 0.f;
        float dd = am - cc;
        num += dd * gg;
        den += dd * (S - gg - qq);
    }
    __shared__ float rn[8][33], rd[8][33], colden[32];
    rn[ty][tx] = num; rd[ty][tx] = den;
    __syncthreads();
    if (ty == 0) {
        float n2 = 0.f, d2 = 0.f;
        for (int t = 0; t < 8; t++) { n2 += rn[t][tx]; d2 += rd[t][tx]; }
        g_num[j] = n2; colden[tx] = d2;
    }
    __syncthreads();
    if (tid == 0) {
        float d3 = 0.f;
        for (int t = 0; t < 32; t++) d3 += colden[t];
        g_denpart[blockIdx.x] = d3;
    }
}

__global__ void __launch_bounds__(256) nd_update_kernel() {
    const int tx = threadIdx.x, ty = threadIdx.y, tid = ty * 32 + tx;
    const int j0 = blockIdx.x * 32, j = j0 + tx;
    __shared__ float red[256];
    __shared__ int amin_s[AD];
    __shared__ int sel_a[AD], sel_j[AD], nsel_s;
    red[tid] = g_denpart[tid] + g_denpart[tid + 256];
    for (int a = tid; a < AD; a += 256) amin_s[a] = g_amin[a];
    __syncthreads();
    for (int o = 128; o; o >>= 1) {
        if (tid < o) red[tid] += red[tid + o];
        __syncthreads();
    }
    build_sel_list(amin_s, j0, sel_a, sel_j, &nsel_s, tid, tx);
    __syncthreads();
    const int ns = nsel_s;
    const float denom = red[0] + EPSC;
    const float lam = fminf(fmaxf(-g_num[j] / denom, 0.f), 1.f);

    for (int a = ty; a < AD; a += 8) {
        size_t idx = (size_t)a * BD + j;
        float cc = g_c[idx], gg = g_grad[idx], qq = g_q[idx];
        float S = 0.f;
        for (int e = 0; e < ns; e++)
            if (sel_j[e] == j) S += g_X[a * AD + sel_a[e]];
        float am = (amin_s[a] == j) ? 1.f : 0.f;
        float dd = am - cc;
        float xd = S - gg - qq;
        g_c[idx]   = cc + lam * dd;
        g_grad[idx] = gg + lam * xd;
    }
}

// =====================================================================
// softmax: writes normal-layout g_sm AND transposed rna-tf32 operand
// =====================================================================
__global__ void __launch_bounds__(256) softmaxT_kernel() {
    const int tx = threadIdx.x, ty = threadIdx.y;
    const int j0 = blockIdx.x * 32, j = j0 + tx;
    float m = -INFINITY, s = 0.f;
    for (int a = ty; a < AD; a += 8) {
        float v = -TEMPC * g_grad[(size_t)a * BD + j];
        if (v > m) { s = s * expf(m - v) + 1.f; m = v; }
        else        s += expf(v - m);
    }
    __shared__ float mm[8][33], ss[8][33], fm[32], fs[32];
    mm[ty][tx] = m; ss[ty][tx] = s;
    __syncthreads();
    if (ty == 0) {
        float M = mm[0][tx], S = ss[0][tx];
        for (int t = 1; t < 8; t++) {
            float m2 = mm[t][tx], s2 = ss[t][tx];
            float Mn = fmaxf(M, m2);
            S = S * expf(M - Mn) + s2 * expf(m2 - Mn);
            M = Mn;
        }
        fm[tx] = M; fs[tx] = S;
    }
    __syncthreads();
    const float M = fm[tx];
    const float invS = 1.0f / fs[tx];

    __shared__ float th[32][33];
    for (int at = 0; at < 32; at++) {
        const int a0 = at * 32;
        for (int aa = ty; aa < 32; aa += 8) {
            size_t idx = (size_t)(a0 + aa) * BD + j;
            float v = -TEMPC * g_grad[idx];
            float e = expf(v - M) * invS;
            g_sm[idx] = e;
            th[aa][tx] = tf32_rna(e);
        }
        __syncthreads();
#pragma unroll
        for (int rr = 0; rr < 4; rr++) {
            int r = ty * 4 + rr;
            g_smT_h[(size_t)(j0 + r) * AD + a0 + tx] = th[tx][r];
        }
        __syncthreads();
    }
}

__global__ void __launch_bounds__(256) d_reduce_kernel() {
    const int tx = threadIdx.x, ty = threadIdx.y, tid = ty * 32 + tx;
    const int j = blockIdx.x * 32 + tx;
    float num = 0.f, den = 0.f;
    for (int a = ty; a < AD; a += 8) {
        size_t idx = (size_t)a * BD + j;
        float dd = g_sm[idx] - g_c[idx];
        float xd = g_xsm[idx] - g_grad[idx] - g_q[idx];
        num += dd * g_grad[idx];
        den += dd * xd;
    }
    __shared__ float rn[8][33], rd[8][33], colden[32];
    rn[ty][tx] = num; rd[ty][tx] = den;
    __syncthreads();
    if (ty == 0) {
        float n2 = 0.f, d2 = 0.f;
        for (int t = 0; t < 8; t++) { n2 += rn[t][tx]; d2 += rd[t][tx]; }
        g_num[j] = n2; colden[tx] = d2;
    }
    __syncthreads();
    if (tid == 0) {
        float d3 = 0.f;
        for (int t = 0; t < 32; t++) d3 += colden[t];
        g_denpart[blockIdx.x] = d3;
    }
}

__global__ void __launch_bounds__(256) d_update_kernel() {
    const int tx = threadIdx.x, ty = threadIdx.y, tid = ty * 32 + tx;
    const int j = blockIdx.x * 32 + tx;
    __shared__ float red[256];
    red[tid] = g_denpart[tid] + g_denpart[tid + 256];
    __syncthreads();
    for (int o = 128; o; o >>= 1) {
        if (tid < o) red[tid] += red[tid + o];
        __syncthreads();
    }
    const float denom = red[0] + EPSC;
    const float lam = fminf(fmaxf(-g_num[j] / denom, 0.f), 1.f);
    for (int a = ty; a < AD; a += 8) {
        size_t idx = (size_t)a * BD + j;
        float cc = g_c[idx], gg = g_grad[idx];
        float dd = g_sm[idx] - cc;
        float xd = g_xsm[idx] - gg - g_q[idx];
        g_c[idx]   = cc + lam * dd;
        g_grad[idx] = gg + lam * xd;
    }
}

// =====================================================================
// host launcher
// =====================================================================
extern "C" void kernel_launch(void* const* d_in, const int* in_sizes, int n_in,
                              void* d_out, int out_size)
{
    const float* y     = (const float*)d_in[0];
    const float* atoms = (const float*)d_in[1];
    float* out = (float*)d_out;

    float *p_anorm, *p_X, *p_q, *p_c, *p_invyn, *p_ynorm;
    cudaGetSymbolAddress((void**)&p_anorm, g_anorm);
    cudaGetSymbolAddress((void**)&p_X,     g_X);
    cudaGetSymbolAddress((void**)&p_q,     g_q);
    cudaGetSymbolAddress((void**)&p_c,     g_c);
    cudaGetSymbolAddress((void**)&p_invyn, g_invyn);
    cudaGetSymbolAddress((void**)&p_ynorm, g_ynorm);

    cudaFuncSetAttribute(xsm_wmma_kernel,
                         cudaFuncAttributeMaxDynamicSharedMemorySize, SMEM_DYN);

    ynorm_kernel<<<BD / 8, 256>>>(y);
    anorm_kernel<<<AD, 256>>>(atoms);

    gemm_kernel<false, false, 0><<<dim3(AD / 128, AD / 128), 256>>>(
        p_anorm, p_anorm, p_X, AD, AD, DD, DD, DD, AD, nullptr);
    rowsumX_kernel<<<AD / 8, 256>>>();
    xsplit_kernel<<<(AD * AD) / 1024, 256>>>();

    gemm_kernel<false, false, 1><<<dim3(BD / 128, AD / 128), 256>>>(
        p_anorm, y, p_q, AD, BD, DD, DD, DD, BD, p_invyn);

    init_kernel<<<(AD * BD) / 1024, 256>>>();

    for (int s = 0; s < NONDIFF; s++) {
        argmin_kernel<<<AD, 256>>>();
        nd_reduce_kernel<<<BD / 32, dim3(32, 8)>>>();
        nd_update_kernel<<<BD / 32, dim3(32, 8)>>>();
    }

    for (int s = 0; s < DIFFST; s++) {
        softmaxT_kernel<<<BD / 32, dim3(32, 8)>>>();
        xsm_wmma_kernel<<<dim3(BD / 128, AD / 128), 256, SMEM_DYN>>>();
        d_reduce_kernel<<<BD / 32, dim3(32, 8)>>>();
        d_update_kernel<<<BD / 32, dim3(32, 8)>>>();
    }

    gemm_kernel<true, true, 2><<<dim3(DD / 128, BD / 128), 256>>>(
        p_c, p_anorm, out, BD, DD, AD, BD, DD, DD, p_ynorm);
}

// round 8
// speedup vs baseline: 1.7339x; 1.2238x over previous
#include <cuda_runtime.h>
#include <mma.h>
#include <math.h>
#include <stdint.h>

using namespace nvcuda;

#define AD 1024
#define BD 16384
#define DD 768
#define TEMPC 100.0f
#define EPSC 1e-8f
#define NONDIFF 30
#define DIFFST 10
#define NBLK 256            /* BD / 64 column blocks */

// ---- device scratch (allocation-free: __device__ globals) ----
__device__ float g_anorm[AD * DD];
__device__ float g_X[AD * AD];
__device__ float g_Xh[AD * AD];          // rna-tf32 rounded X
__device__ float g_rsx[AD];
__device__ float g_q[AD * BD];
__device__ float g_c[AD * BD];
__device__ float g_grad[AD * BD];
__device__ float g_sm[AD * BD];
__device__ float g_smT_h[(size_t)BD * AD];   // transposed rna-tf32 softmax [n][k]
__device__ float g_xsm[AD * BD];
__device__ float g_ynorm[BD];
__device__ float g_invyn[BD];
__device__ int   g_amin[AD];
__device__ float g_num[BD];
__device__ float g_denpart[NBLK];
__device__ unsigned long long g_minp[AD * NBLK];   // 2 MB packed min partials

__device__ __forceinline__ float tf32_rna(float x) {
    float r;
    asm("cvt.rna.tf32.f32 %0, %1;" : "=f"(r) : "f"(x));
    return r;
}
__device__ __forceinline__ uint32_t smem_u32(const void* p) {
    uint32_t a;
    asm("{ .reg .u64 t; cvta.to.shared.u64 t, %1; cvt.u32.u64 %0, t; }" : "=r"(a) : "l"(p));
    return a;
}
// order-preserving float->uint encode (monotone: enc(a) < enc(b) <=> a < b)
__device__ __forceinline__ unsigned fenc(float v) {
    unsigned b = __float_as_uint(v);
    return b ^ ((b & 0x80000000u) ? 0xFFFFFFFFu : 0x80000000u);
}
__device__ __forceinline__ unsigned long long packmin(float v, int j) {
    return ((unsigned long long)fenc(v) << 32) | (unsigned)j;
}
#define CP16(dst, src) asm volatile("cp.async.cg.shared.global [%0], [%1], 16;" :: "r"(dst), "l"(src))
#define CP_COMMIT()    asm volatile("cp.async.commit_group;" ::: "memory")
#define CP_WAIT(n)     asm volatile("cp.async.wait_group %0;" :: "n"(n) : "memory")

// =====================================================================
// init kernels
// =====================================================================
__global__ void ynorm_kernel(const float* __restrict__ y) {
    int w = (blockIdx.x * blockDim.x + threadIdx.x) >> 5;
    int lane = threadIdx.x & 31;
    if (w >= BD) return;
    const float* row = y + (size_t)w * DD;
    float s = 0.f;
    for (int d = lane; d < DD; d += 32) s += fabsf(row[d]);
#pragma unroll
    for (int o = 16; o; o >>= 1) s += __shfl_xor_sync(0xffffffffu, s, o);
    if (!lane) { g_ynorm[w] = s; g_invyn[w] = 1.0f / s; }
}

__global__ void anorm_kernel(const float* __restrict__ atoms) {
    int r = blockIdx.x;
    const float* row = atoms + (size_t)r * DD;
    __shared__ float red[256];
    float s = 0.f;
    for (int d = threadIdx.x; d < DD; d += 256) s += fabsf(row[d]);
    red[threadIdx.x] = s;
    __syncthreads();
    for (int o = 128; o; o >>= 1) {
        if (threadIdx.x < o) red[threadIdx.x] += red[threadIdx.x + o];
        __syncthreads();
    }
    float nrm = red[0];
    for (int d = threadIdx.x; d < DD; d += 256)
        g_anorm[r * DD + d] = row[d] / nrm;
}

__global__ void rowsumX_kernel() {
    int w = (blockIdx.x * blockDim.x + threadIdx.x) >> 5;
    int lane = threadIdx.x & 31;
    if (w >= AD) return;
    float s = 0.f;
    for (int k = lane; k < AD; k += 32) s += g_X[w * AD + k];
#pragma unroll
    for (int o = 16; o; o >>= 1) s += __shfl_xor_sync(0xffffffffu, s, o);
    if (!lane) g_rsx[w] = s;
}

__global__ void xsplit_kernel() {
    size_t i = ((size_t)blockIdx.x * 256 + threadIdx.x) * 4;
    float4 x = *reinterpret_cast<const float4*>(g_X + i);
    float4 h;
    h.x = tf32_rna(x.x); h.y = tf32_rna(x.y);
    h.z = tf32_rna(x.z); h.w = tf32_rna(x.w);
    *reinterpret_cast<float4*>(g_Xh + i) = h;
}

__global__ void init_kernel() {
    size_t i4 = ((size_t)blockIdx.x * 256 + threadIdx.x) * 4;
    int a = (int)(i4 / BD);
    float rs = g_rsx[a] * (1.0f / AD);
    float4 q4 = *reinterpret_cast<const float4*>(g_q + i4);
    float4 g;
    g.x = rs - q4.x; g.y = rs - q4.y; g.z = rs - q4.z; g.w = rs - q4.w;
    *reinterpret_cast<float4*>(g_grad + i4) = g;
    float4 cc = make_float4(1.0f / AD, 1.0f / AD, 1.0f / AD, 1.0f / AD);
    *reinterpret_cast<float4*>(g_c + i4) = cc;
}

// =====================================================================
// fp32 SIMT GEMM (X, q, recon)
// =====================================================================
template <bool AKM, bool BKM, int SCALE>
__global__ void __launch_bounds__(256) gemm_kernel(
    const float* __restrict__ A, const float* __restrict__ B, float* __restrict__ C,
    int M, int N, int K, int lda, int ldb, int ldc, const float* __restrict__ scale)
{
    __shared__ float As[16][132];
    __shared__ float Bs[16][132];
    const int tid = threadIdx.x;
    const int tx = tid & 15, ty = tid >> 4;
    const int m0 = blockIdx.y * 128, n0 = blockIdx.x * 128;
    float acc[8][8];
#pragma unroll
    for (int i = 0; i < 8; i++)
#pragma unroll
        for (int j = 0; j < 8; j++) acc[i][j] = 0.f;

    for (int k0 = 0; k0 < K; k0 += 16) {
#pragma unroll
        for (int i = 0; i < 2; i++) {
            int lin = tid + i * 256;
            if (AKM) {
                int kk = lin >> 5, mm = (lin & 31) << 2;
                float4 v = *reinterpret_cast<const float4*>(A + (size_t)(k0 + kk) * lda + (m0 + mm));
                *reinterpret_cast<float4*>(&As[kk][mm]) = v;
            } else {
                int mm = lin >> 2, kk = (lin & 3) << 2;
                float4 v = *reinterpret_cast<const float4*>(A + (size_t)(m0 + mm) * lda + (k0 + kk));
                As[kk + 0][mm] = v.x; As[kk + 1][mm] = v.y;
                As[kk + 2][mm] = v.z; As[kk + 3][mm] = v.w;
            }
        }
#pragma unroll
        for (int i = 0; i < 2; i++) {
            int lin = tid + i * 256;
            if (BKM) {
                int kk = lin >> 5, nn = (lin & 31) << 2;
                float4 v = *reinterpret_cast<const float4*>(B + (size_t)(k0 + kk) * ldb + (n0 + nn));
                *reinterpret_cast<float4*>(&Bs[kk][nn]) = v;
            } else {
                int nn = lin >> 2, kk = (lin & 3) << 2;
                float4 v = *reinterpret_cast<const float4*>(B + (size_t)(n0 + nn) * ldb + (k0 + kk));
                Bs[kk + 0][nn] = v.x; Bs[kk + 1][nn] = v.y;
                Bs[kk + 2][nn] = v.z; Bs[kk + 3][nn] = v.w;
            }
        }
        __syncthreads();
#pragma unroll
        for (int k = 0; k < 16; k++) {
            float af[8], bf[8];
            *reinterpret_cast<float4*>(&af[0]) = *reinterpret_cast<float4*>(&As[k][ty * 8]);
            *reinterpret_cast<float4*>(&af[4]) = *reinterpret_cast<float4*>(&As[k][ty * 8 + 4]);
            *reinterpret_cast<float4*>(&bf[0]) = *reinterpret_cast<float4*>(&Bs[k][tx * 8]);
            *reinterpret_cast<float4*>(&bf[4]) = *reinterpret_cast<float4*>(&Bs[k][tx * 8 + 4]);
#pragma unroll
            for (int i = 0; i < 8; i++)
#pragma unroll
                for (int j = 0; j < 8; j++) acc[i][j] += af[i] * bf[j];
        }
        __syncthreads();
    }
#pragma unroll
    for (int i = 0; i < 8; i++) {
        int m = m0 + ty * 8 + i;
        float rowf = (SCALE == 2) ? scale[m] : 1.f;
#pragma unroll
        for (int j = 0; j < 8; j++) {
            float f = (SCALE == 1) ? scale[n0 + tx * 8 + j] : rowf;
            C[(size_t)m * ldc + n0 + tx * 8 + j] = acc[i][j] * f;
        }
    }
}

// =====================================================================
// xsm = Xh @ smT_h^T : tf32 wmma (unchanged from R7)
// =====================================================================
#define LDS_PAD 36
#define ARR_B   (128 * LDS_PAD * 4)
#define BUF_B   (2 * ARR_B)
#define SMEM_DYN (2 * BUF_B)

__global__ void __launch_bounds__(256, 2) xsm_wmma_kernel() {
    extern __shared__ float smf[];
    const uint32_t sb = smem_u32(smf);
    const int tid = threadIdx.x;
    const int wid = tid >> 5;
    const int m0 = blockIdx.y * 128;
    const int n0 = blockIdx.x * 128;
    const int wm = (wid >> 1) * 32;
    const int wn = (wid & 1) * 64;

    const float* srcA = g_Xh    + (size_t)m0 * AD;
    const float* srcB = g_smT_h + (size_t)n0 * AD;

    wmma::fragment<wmma::accumulator, 16, 16, 8, float> acc[2][4];
#pragma unroll
    for (int i = 0; i < 2; i++)
#pragma unroll
        for (int j = 0; j < 4; j++) wmma::fill_fragment(acc[i][j], 0.0f);

#define PREFETCH(CK, BUF) do { \
    const int _k0 = (CK) * 32; \
    _Pragma("unroll") \
    for (int s = 0; s < 4; s++) { \
        int seg = tid + s * 256; \
        int row = seg >> 3, sg = seg & 7; \
        uint32_t off = (uint32_t)(row * LDS_PAD + sg * 4) * 4; \
        CP16(sb + (BUF) * BUF_B + off,         srcA + (size_t)row * AD + _k0 + sg * 4); \
        CP16(sb + (BUF) * BUF_B + ARR_B + off, srcB + (size_t)row * AD + _k0 + sg * 4); \
    } \
    CP_COMMIT(); } while (0)

    PREFETCH(0, 0);

    const int NCK = AD / 32;
    for (int ck = 0; ck < NCK; ck++) {
        const int buf = ck & 1;
        if (ck + 1 < NCK) {
            PREFETCH(ck + 1, (ck + 1) & 1);
            CP_WAIT(1);
        } else {
            CP_WAIT(0);
        }
        __syncthreads();

        const float* At = smf + (buf * BUF_B) / 4;
        const float* Bt = smf + (buf * BUF_B + ARR_B) / 4;

#pragma unroll
        for (int ks = 0; ks < 4; ks++) {
            wmma::fragment<wmma::matrix_a, 16, 16, 8, wmma::precision::tf32, wmma::row_major> af[2];
            wmma::fragment<wmma::matrix_b, 16, 16, 8, wmma::precision::tf32, wmma::col_major> bf[4];
#pragma unroll
            for (int i = 0; i < 2; i++)
                wmma::load_matrix_sync(af[i], At + (wm + i * 16) * LDS_PAD + ks * 8, LDS_PAD);
#pragma unroll
            for (int j = 0; j < 4; j++)
                wmma::load_matrix_sync(bf[j], Bt + (wn + j * 16) * LDS_PAD + ks * 8, LDS_PAD);
#pragma unroll
            for (int i = 0; i < 2; i++)
#pragma unroll
                for (int j = 0; j < 4; j++)
                    wmma::mma_sync(acc[i][j], af[i], bf[j], acc[i][j]);
        }
        __syncthreads();
    }
#undef PREFETCH

#pragma unroll
    for (int i = 0; i < 2; i++)
#pragma unroll
        for (int j = 0; j < 4; j++) {
            float* dst = g_xsm + (size_t)(m0 + wm + i * 16) * BD + (n0 + wn + j * 16);
            wmma::store_matrix_sync(dst, acc[i][j], BD, wmma::mem_row_major);
        }
}

// =====================================================================
// full argmin (step 0 only): first-occurrence min per atom row
// =====================================================================
__global__ void __launch_bounds__(256) argmin_full_kernel() {
    const int a = blockIdx.x;
    const float* row = g_grad + (size_t)a * BD;
    unsigned long long best = ~0ull;
    for (int it = 0; it < 16; it++) {
        int j = threadIdx.x * 4 + it * 1024;
        float4 v = *reinterpret_cast<const float4*>(row + j);
        unsigned long long k0 = packmin(v.x, j);
        unsigned long long k1 = packmin(v.y, j + 1);
        unsigned long long k2 = packmin(v.z, j + 2);
        unsigned long long k3 = packmin(v.w, j + 3);
        if (k1 < k0) k0 = k1;
        if (k3 < k2) k2 = k3;
        if (k2 < k0) k0 = k2;
        if (k0 < best) best = k0;
    }
    __shared__ unsigned long long sk[256];
    sk[threadIdx.x] = best;
    __syncthreads();
    for (int o = 128; o; o >>= 1) {
        if (threadIdx.x < o && sk[threadIdx.x + o] < sk[threadIdx.x])
            sk[threadIdx.x] = sk[threadIdx.x + o];
        __syncthreads();
    }
    if (!threadIdx.x) g_amin[a] = (int)(sk[0] & 0xFFFFFFFFu);
}

// reduce per-block min partials (written by nd_update) to g_amin
__global__ void __launch_bounds__(256) argmin_parts_kernel() {
    const int wid = threadIdx.x >> 5, lane = threadIdx.x & 31;
    const int a = blockIdx.x * 8 + wid;
    unsigned long long best = ~0ull;
#pragma unroll
    for (int k = 0; k < NBLK / 32; k++) {
        unsigned long long v = g_minp[(size_t)a * NBLK + lane + k * 32];
        if (v < best) best = v;
    }
#pragma unroll
    for (int o = 16; o; o >>= 1) {
        unsigned long long v = __shfl_down_sync(0xffffffffu, best, o);
        if (v < best) best = v;
    }
    if (!lane) g_amin[a] = (int)(best & 0xFFFFFFFFu);
}

// =====================================================================
// selection list: atoms whose argmin lands in this 64-col window
// =====================================================================
__device__ __forceinline__ void build_sel_list(
    const int* amin_s, int j0, int* sel_a, int* sel_j, int* nsel_s,
    int tid)
{
    if (tid < 32) {
        int cnt = 0;
        for (int base = 0; base < AD; base += 32) {
            int a = base + tid;
            int jm = amin_s[a];
            bool mt = (jm >= j0 && jm < j0 + 64);
            unsigned mask = __ballot_sync(0xffffffffu, mt);
            if (mt) {
                int p = cnt + __popc(mask & ((1u << tid) - 1u));
                sel_a[p] = a; sel_j[p] = jm;
            }
            cnt += __popc(mask);
        }
        if (tid == 0) *nsel_s = cnt;
    }
}

// =====================================================================
// nondiff step kernels: 64 cols/block, float4 per thread
// block 256: tx = tid&15 (4 cols each), ty = tid>>4 (16 a-strides)
// =====================================================================
__global__ void __launch_bounds__(256) nd_reduce_kernel() {
    const int tid = threadIdx.x, tx = tid & 15, ty = tid >> 4;
    const int j0 = blockIdx.x * 64, jb = j0 + tx * 4;
    __shared__ int amin_s[AD];
    __shared__ int sel_a[AD], sel_j[AD], nsel_s;
    for (int a = tid; a < AD; a += 256) amin_s[a] = g_amin[a];
    __syncthreads();
    build_sel_list(amin_s, j0, sel_a, sel_j, &nsel_s, tid);
    __syncthreads();
    const int ns = nsel_s;

    float4 num4 = {0, 0, 0, 0}, den4 = {0, 0, 0, 0};
    for (int a = ty; a < AD; a += 16) {
        size_t idx = (size_t)a * BD + jb;
        float4 cc = *reinterpret_cast<const float4*>(g_c + idx);
        float4 gg = *reinterpret_cast<const float4*>(g_grad + idx);
        float4 qq = *reinterpret_cast<const float4*>(g_q + idx);
        float4 S = {0, 0, 0, 0};
        for (int e = 0; e < ns; e++) {
            float xv = g_X[a * AD + sel_a[e]];
            int d = sel_j[e] - jb;
            S.x += (d == 0) ? xv : 0.f;
            S.y += (d == 1) ? xv : 0.f;
            S.z += (d == 2) ? xv : 0.f;
            S.w += (d == 3) ? xv : 0.f;
        }
        int am = amin_s[a];
        float4 dd, xd;
        dd.x = ((am == jb + 0) ? 1.f : 0.f) - cc.x;
        dd.y = ((am == jb + 1) ? 1.f : 0.f) - cc.y;
        dd.z = ((am == jb + 2) ? 1.f : 0.f) - cc.z;
        dd.w = ((am == jb + 3) ? 1.f : 0.f) - cc.w;
        xd.x = S.x - gg.x - qq.x; xd.y = S.y - gg.y - qq.y;
        xd.z = S.z - gg.z - qq.z; xd.w = S.w - gg.w - qq.w;
        num4.x += dd.x * gg.x; num4.y += dd.y * gg.y;
        num4.z += dd.z * gg.z; num4.w += dd.w * gg.w;
        den4.x += dd.x * xd.x; den4.y += dd.y * xd.y;
        den4.z += dd.z * xd.z; den4.w += dd.w * xd.w;
    }
    __shared__ float4 rn[16][17], rd[16][17];
    __shared__ float colden[16];
    rn[ty][tx] = num4; rd[ty][tx] = den4;
    __syncthreads();
    if (ty == 0) {
        float4 n = rn[0][tx], d = rd[0][tx];
        for (int t = 1; t < 16; t++) {
            float4 n2 = rn[t][tx], d2 = rd[t][tx];
            n.x += n2.x; n.y += n2.y; n.z += n2.z; n.w += n2.w;
            d.x += d2.x; d.y += d2.y; d.z += d2.z; d.w += d2.w;
        }
        *reinterpret_cast<float4*>(g_num + jb) = n;
        colden[tx] = d.x + d.y + d.z + d.w;
    }
    __syncthreads();
    if (tid == 0) {
        float s = 0.f;
        for (int t = 0; t < 16; t++) s += colden[t];
        g_denpart[blockIdx.x] = s;
    }
}

__global__ void __launch_bounds__(256) nd_update_kernel() {
    const int tid = threadIdx.x, tx = tid & 15, ty = tid >> 4;
    const int j0 = blockIdx.x * 64, jb = j0 + tx * 4;
    __shared__ float red[256];
    __shared__ int amin_s[AD];
    __shared__ int sel_a[AD], sel_j[AD], nsel_s;
    red[tid] = g_denpart[tid];
    for (int a = tid; a < AD; a += 256) amin_s[a] = g_amin[a];
    __syncthreads();
    for (int o = 128; o; o >>= 1) {
        if (tid < o) red[tid] += red[tid + o];
        __syncthreads();
    }
    build_sel_list(amin_s, j0, sel_a, sel_j, &nsel_s, tid);
    __syncthreads();
    const int ns = nsel_s;
    const float denom = red[0] + EPSC;
    float4 nm = *reinterpret_cast<const float4*>(g_num + jb);
    float4 lam;
    lam.x = fminf(fmaxf(-nm.x / denom, 0.f), 1.f);
    lam.y = fminf(fmaxf(-nm.y / denom, 0.f), 1.f);
    lam.z = fminf(fmaxf(-nm.z / denom, 0.f), 1.f);
    lam.w = fminf(fmaxf(-nm.w / denom, 0.f), 1.f);

    for (int a = ty; a < AD; a += 16) {
        size_t idx = (size_t)a * BD + jb;
        float4 cc = *reinterpret_cast<const float4*>(g_c + idx);
        float4 gg = *reinterpret_cast<const float4*>(g_grad + idx);
        float4 qq = *reinterpret_cast<const float4*>(g_q + idx);
        float4 S = {0, 0, 0, 0};
        for (int e = 0; e < ns; e++) {
            float xv = g_X[a * AD + sel_a[e]];
            int d = sel_j[e] - jb;
            S.x += (d == 0) ? xv : 0.f;
            S.y += (d == 1) ? xv : 0.f;
            S.z += (d == 2) ? xv : 0.f;
            S.w += (d == 3) ? xv : 0.f;
        }
        int am = amin_s[a];
        float4 dd, xd, c2, g2;
        dd.x = ((am == jb + 0) ? 1.f : 0.f) - cc.x;
        dd.y = ((am == jb + 1) ? 1.f : 0.f) - cc.y;
        dd.z = ((am == jb + 2) ? 1.f : 0.f) - cc.z;
        dd.w = ((am == jb + 3) ? 1.f : 0.f) - cc.w;
        xd.x = S.x - gg.x - qq.x; xd.y = S.y - gg.y - qq.y;
        xd.z = S.z - gg.z - qq.z; xd.w = S.w - gg.w - qq.w;
        c2.x = cc.x + lam.x * dd.x; c2.y = cc.y + lam.y * dd.y;
        c2.z = cc.z + lam.z * dd.z; c2.w = cc.w + lam.w * dd.w;
        g2.x = gg.x + lam.x * xd.x; g2.y = gg.y + lam.y * xd.y;
        g2.z = gg.z + lam.z * xd.z; g2.w = gg.w + lam.w * xd.w;
        *reinterpret_cast<float4*>(g_c + idx)    = c2;
        *reinterpret_cast<float4*>(g_grad + idx) = g2;

        // fused row-min partial over this block's 64 columns (new grad)
        unsigned long long best = packmin(g2.x, jb);
        unsigned long long k1 = packmin(g2.y, jb + 1);
        unsigned long long k2 = packmin(g2.z, jb + 2);
        unsigned long long k3 = packmin(g2.w, jb + 3);
        if (k1 < best) best = k1;
        if (k2 < best) best = k2;
        if (k3 < best) best = k3;
#pragma unroll
        for (int o = 8; o; o >>= 1) {
            unsigned long long v = __shfl_down_sync(0xffffffffu, best, o, 16);
            if (v < best) best = v;
        }
        if (tx == 0) g_minp[(size_t)a * NBLK + blockIdx.x] = best;
    }
}

// =====================================================================
// softmax (vectorized) + transposed rna-tf32 operand
// =====================================================================
__global__ void __launch_bounds__(256) softmaxT_kernel() {
    const int tid = threadIdx.x, tx = tid & 15, ty = tid >> 4;
    const int j0 = blockIdx.x * 64, jb = j0 + tx * 4;

    // pass 1: online max/sum per column
    float4 m4 = {-INFINITY, -INFINITY, -INFINITY, -INFINITY};
    float4 s4 = {0, 0, 0, 0};
    for (int a = ty; a < AD; a += 16) {
        float4 g = *reinterpret_cast<const float4*>(g_grad + (size_t)a * BD + jb);
        float v;
        v = -TEMPC * g.x; if (v > m4.x) { s4.x = s4.x * expf(m4.x - v) + 1.f; m4.x = v; } else s4.x += expf(v - m4.x);
        v = -TEMPC * g.y; if (v > m4.y) { s4.y = s4.y * expf(m4.y - v) + 1.f; m4.y = v; } else s4.y += expf(v - m4.y);
        v = -TEMPC * g.z; if (v > m4.z) { s4.z = s4.z * expf(m4.z - v) + 1.f; m4.z = v; } else s4.z += expf(v - m4.z);
        v = -TEMPC * g.w; if (v > m4.w) { s4.w = s4.w * expf(m4.w - v) + 1.f; m4.w = v; } else s4.w += expf(v - m4.w);
    }
    __shared__ float4 mm[16][17], ss[16][17];
    __shared__ float4 fm[16], fsinv[16];
    mm[ty][tx] = m4; ss[ty][tx] = s4;
    __syncthreads();
    if (ty == 0) {
        float4 M = mm[0][tx], S = ss[0][tx];
        for (int t = 1; t < 16; t++) {
            float4 m2 = mm[t][tx], s2 = ss[t][tx];
            float Mn;
            Mn = fmaxf(M.x, m2.x); S.x = S.x * expf(M.x - Mn) + s2.x * expf(m2.x - Mn); M.x = Mn;
            Mn = fmaxf(M.y, m2.y); S.y = S.y * expf(M.y - Mn) + s2.y * expf(m2.y - Mn); M.y = Mn;
            Mn = fmaxf(M.z, m2.z); S.z = S.z * expf(M.z - Mn) + s2.z * expf(m2.z - Mn); M.z = Mn;
            Mn = fmaxf(M.w, m2.w); S.w = S.w * expf(M.w - Mn) + s2.w * expf(m2.w - Mn); M.w = Mn;
        }
        fm[tx] = M;
        fsinv[tx] = make_float4(1.f / S.x, 1.f / S.y, 1.f / S.z, 1.f / S.w);
    }
    __syncthreads();
    const float4 M4 = fm[tx];
    const float4 I4 = fsinv[tx];

    // pass 2: write sm (normal layout) + smT (transposed, tf32-rounded)
    __shared__ float tile[32][68];
    const int jloc_w = tid >> 2;           // 0..63
    const int qw = tid & 3;                // a-subrange
    for (int at = 0; at < 32; at++) {
        const int a0 = at * 32;
#pragma unroll
        for (int half = 0; half < 2; half++) {
            int aa = ty + half * 16;
            size_t idx = (size_t)(a0 + aa) * BD + jb;
            float4 g = *reinterpret_cast<const float4*>(g_grad + idx);
            float4 e;
            e.x = expf(-TEMPC * g.x - M4.x) * I4.x;
            e.y = expf(-TEMPC * g.y - M4.y) * I4.y;
            e.z = expf(-TEMPC * g.z - M4.z) * I4.z;
            e.w = expf(-TEMPC * g.w - M4.w) * I4.w;
            *reinterpret_cast<float4*>(g_sm + idx) = e;
            tile[aa][tx * 4 + 0] = tf32_rna(e.x);
            tile[aa][tx * 4 + 1] = tf32_rna(e.y);
            tile[aa][tx * 4 + 2] = tf32_rna(e.z);
            tile[aa][tx * 4 + 3] = tf32_rna(e.w);
        }
        __syncthreads();
        float* dst = g_smT_h + (size_t)(j0 + jloc_w) * AD + a0 + qw * 8;
        float v[8];
#pragma unroll
        for (int i = 0; i < 8; i++) v[i] = tile[qw * 8 + i][jloc_w];
        *reinterpret_cast<float4*>(dst)     = *reinterpret_cast<float4*>(&v[0]);
        *reinterpret_cast<float4*>(dst + 4) = *reinterpret_cast<float4*>(&v[4]);
        __syncthreads();
    }
}

// =====================================================================
// diff step reduce / update (vectorized)
// =====================================================================
__global__ void __launch_bounds__(256) d_reduce_kernel() {
    const int tid = threadIdx.x, tx = tid & 15, ty = tid >> 4;
    const int jb = blockIdx.x * 64 + tx * 4;
    float4 num4 = {0, 0, 0, 0}, den4 = {0, 0, 0, 0};
    for (int a = ty; a < AD; a += 16) {
        size_t idx = (size_t)a * BD + jb;
        float4 sm = *reinterpret_cast<const float4*>(g_sm + idx);
        float4 cc = *reinterpret_cast<const float4*>(g_c + idx);
        float4 xs = *reinterpret_cast<const float4*>(g_xsm + idx);
        float4 gg = *reinterpret_cast<const float4*>(g_grad + idx);
        float4 qq = *reinterpret_cast<const float4*>(g_q + idx);
        float4 dd, xd;
        dd.x = sm.x - cc.x; dd.y = sm.y - cc.y; dd.z = sm.z - cc.z; dd.w = sm.w - cc.w;
        xd.x = xs.x - gg.x - qq.x; xd.y = xs.y - gg.y - qq.y;
        xd.z = xs.z - gg.z - qq.z; xd.w = xs.w - gg.w - qq.w;
        num4.x += dd.x * gg.x; num4.y += dd.y * gg.y;
        num4.z += dd.z * gg.z; num4.w += dd.w * gg.w;
        den4.x += dd.x * xd.x; den4.y += dd.y * xd.y;
        den4.z += dd.z * xd.z; den4.w += dd.w * xd.w;
    }
    __shared__ float4 rn[16][17], rd[16][17];
    __shared__ float colden[16];
    rn[ty][tx] = num4; rd[ty][tx] = den4;
    __syncthreads();
    if (ty == 0) {
        float4 n = rn[0][tx], d = rd[0][tx];
        for (int t = 1; t < 16; t++) {
            float4 n2 = rn[t][tx], d2 = rd[t][tx];
            n.x += n2.x; n.y += n2.y; n.z += n2.z; n.w += n2.w;
            d.x += d2.x; d.y += d2.y; d.z += d2.z; d.w += d2.w;
        }
        *reinterpret_cast<float4*>(g_num + jb) = n;
        colden[tx] = d.x + d.y + d.z + d.w;
    }
    __syncthreads();
    if (tid == 0) {
        float s = 0.f;
        for (int t = 0; t < 16; t++) s += colden[t];
        g_denpart[blockIdx.x] = s;
    }
}

template <bool LAST>
__global__ void __launch_bounds__(256) d_update_kernel() {
    const int tid = threadIdx.x, tx = tid & 15, ty = tid >> 4;
    const int jb = blockIdx.x * 64 + tx * 4;
    __shared__ float red[256];
    red[tid] = g_denpart[tid];
    __syncthreads();
    for (int o = 128; o; o >>= 1) {
        if (tid < o) red[tid] += red[tid + o];
        __syncthreads();
    }
    const float denom = red[0] + EPSC;
    float4 nm = *reinterpret_cast<const float4*>(g_num + jb);
    float4 lam;
    lam.x = fminf(fmaxf(-nm.x / denom, 0.f), 1.f);
    lam.y = fminf(fmaxf(-nm.y / denom, 0.f), 1.f);
    lam.z = fminf(fmaxf(-nm.z / denom, 0.f), 1.f);
    lam.w = fminf(fmaxf(-nm.w / denom, 0.f), 1.f);
    for (int a = ty; a < AD; a += 16) {
        size_t idx = (size_t)a * BD + jb;
        float4 sm = *reinterpret_cast<const float4*>(g_sm + idx);
        float4 cc = *reinterpret_cast<const float4*>(g_c + idx);
        float4 c2;
        c2.x = cc.x + lam.x * (sm.x - cc.x);
        c2.y = cc.y + lam.y * (sm.y - cc.y);
        c2.z = cc.z + lam.z * (sm.z - cc.z);
        c2.w = cc.w + lam.w * (sm.w - cc.w);
        *reinterpret_cast<float4*>(g_c + idx) = c2;
        if (!LAST) {
            float4 xs = *reinterpret_cast<const float4*>(g_xsm + idx);
            float4 gg = *reinterpret_cast<const float4*>(g_grad + idx);
            float4 qq = *reinterpret_cast<const float4*>(g_q + idx);
            float4 g2;
            g2.x = gg.x + lam.x * (xs.x - gg.x - qq.x);
            g2.y = gg.y + lam.y * (xs.y - gg.y - qq.y);
            g2.z = gg.z + lam.z * (xs.z - gg.z - qq.z);
            g2.w = gg.w + lam.w * (xs.w - gg.w - qq.w);
            *reinterpret_cast<float4*>(g_grad + idx) = g2;
        }
    }
}

// =====================================================================
// host launcher
// =====================================================================
extern "C" void kernel_launch(void* const* d_in, const int* in_sizes, int n_in,
                              void* d_out, int out_size)
{
    const float* y     = (const float*)d_in[0];
    const float* atoms = (const float*)d_in[1];
    float* out = (float*)d_out;

    float *p_anorm, *p_X, *p_q, *p_c, *p_invyn, *p_ynorm;
    cudaGetSymbolAddress((void**)&p_anorm, g_anorm);
    cudaGetSymbolAddress((void**)&p_X,     g_X);
    cudaGetSymbolAddress((void**)&p_q,     g_q);
    cudaGetSymbolAddress((void**)&p_c,     g_c);
    cudaGetSymbolAddress((void**)&p_invyn, g_invyn);
    cudaGetSymbolAddress((void**)&p_ynorm, g_ynorm);

    cudaFuncSetAttribute(xsm_wmma_kernel,
                         cudaFuncAttributeMaxDynamicSharedMemorySize, SMEM_DYN);

    ynorm_kernel<<<BD / 8, 256>>>(y);
    anorm_kernel<<<AD, 256>>>(atoms);

    gemm_kernel<false, false, 0><<<dim3(AD / 128, AD / 128), 256>>>(
        p_anorm, p_anorm, p_X, AD, AD, DD, DD, DD, AD, nullptr);
    rowsumX_kernel<<<AD / 8, 256>>>();
    xsplit_kernel<<<(AD * AD) / 1024, 256>>>();

    gemm_kernel<false, false, 1><<<dim3(BD / 128, AD / 128), 256>>>(
        p_anorm, y, p_q, AD, BD, DD, DD, DD, BD, p_invyn);

    init_kernel<<<(AD * BD) / 1024, 256>>>();

    argmin_full_kernel<<<AD, 256>>>();
    for (int s = 0; s < NONDIFF; s++) {
        nd_reduce_kernel<<<NBLK, 256>>>();
        nd_update_kernel<<<NBLK, 256>>>();
        if (s + 1 < NONDIFF) argmin_parts_kernel<<<AD / 8, 256>>>();
    }

    for (int s = 0; s < DIFFST; s++) {
        softmaxT_kernel<<<NBLK, 256>>>();
        xsm_wmma_kernel<<<dim3(BD / 128, AD / 128), 256, SMEM_DYN>>>();
        d_reduce_kernel<<<NBLK, 256>>>();
        if (s + 1 < DIFFST) d_update_kernel<false><<<NBLK, 256>>>();
        else                d_update_kernel<true ><<<NBLK, 256>>>();
    }

    gemm_kernel<true, true, 2><<<dim3(DD / 128, BD / 128), 256>>>(
        p_c, p_anorm, out, BD, DD, AD, BD, DD, DD, p_ynorm);
}

// round 9
// speedup vs baseline: 2.1299x; 1.2284x over previous
#include <cuda_runtime.h>
#include <math.h>
#include <stdint.h>

#define AD 1024
#define BD 16384
#define DD 768
#define TEMPC 100.0f
#define EPSC 1e-8f
#define NONDIFF 30
#define DIFFST 10
#define NBLK 256            /* BD / 64 column blocks */

// ---- device scratch (allocation-free: __device__ globals) ----
__device__ float g_anorm[AD * DD];
__device__ float g_X[AD * AD];
__device__ float g_Xp[AD * AD];              // fragment-order tf32 X
__device__ float g_rsx[AD];
__device__ float g_q[AD * BD];
__device__ float g_c[AD * BD];
__device__ float g_grad[AD * BD];
__device__ float g_sm[AD * BD];
__device__ float g_smTp[(size_t)BD * AD];    // fragment-order tf32 softmax (B operand)
__device__ float g_xsm[AD * BD];
__device__ float g_ynorm[BD];
__device__ float g_invyn[BD];
__device__ int   g_amin[AD];
__device__ float g_num[BD];
__device__ float g_denpart[NBLK];
__device__ unsigned long long g_minp[AD * NBLK];

__device__ __forceinline__ float tf32_rna(float x) {
    float r;
    asm("cvt.rna.tf32.f32 %0, %1;" : "=f"(r) : "f"(x));
    return r;
}
__device__ __forceinline__ uint32_t smem_u32(const void* p) {
    uint32_t a;
    asm("{ .reg .u64 t; cvta.to.shared.u64 t, %1; cvt.u32.u64 %0, t; }" : "=r"(a) : "l"(p));
    return a;
}
__device__ __forceinline__ unsigned fenc(float v) {
    unsigned b = __float_as_uint(v);
    return b ^ ((b & 0x80000000u) ? 0xFFFFFFFFu : 0x80000000u);
}
__device__ __forceinline__ unsigned long long packmin(float v, int j) {
    return ((unsigned long long)fenc(v) << 32) | (unsigned)j;
}
#define CP16(dst, src) asm volatile("cp.async.cg.shared.global [%0], [%1], 16;" :: "r"(dst), "l"(src))
#define CP_COMMIT()    asm volatile("cp.async.commit_group;" ::: "memory")
#define CP_WAIT(n)     asm volatile("cp.async.wait_group %0;" :: "n"(n) : "memory")

__device__ __forceinline__ void mma_tf32_16n8k8(float* c, const uint32_t* a, const uint32_t* b) {
    asm volatile(
        "mma.sync.aligned.m16n8k8.row.col.f32.tf32.tf32.f32 "
        "{%0,%1,%2,%3}, {%4,%5,%6,%7}, {%8,%9}, {%0,%1,%2,%3};"
        : "+f"(c[0]), "+f"(c[1]), "+f"(c[2]), "+f"(c[3])
        : "r"(a[0]), "r"(a[1]), "r"(a[2]), "r"(a[3]), "r"(b[0]), "r"(b[1]));
}

// =====================================================================
// init kernels
// =====================================================================
__global__ void ynorm_kernel(const float* __restrict__ y) {
    int w = (blockIdx.x * blockDim.x + threadIdx.x) >> 5;
    int lane = threadIdx.x & 31;
    if (w >= BD) return;
    const float* row = y + (size_t)w * DD;
    float s = 0.f;
    for (int d = lane; d < DD; d += 32) s += fabsf(row[d]);
#pragma unroll
    for (int o = 16; o; o >>= 1) s += __shfl_xor_sync(0xffffffffu, s, o);
    if (!lane) { g_ynorm[w] = s; g_invyn[w] = 1.0f / s; }
}

__global__ void anorm_kernel(const float* __restrict__ atoms) {
    int r = blockIdx.x;
    const float* row = atoms + (size_t)r * DD;
    __shared__ float red[256];
    float s = 0.f;
    for (int d = threadIdx.x; d < DD; d += 256) s += fabsf(row[d]);
    red[threadIdx.x] = s;
    __syncthreads();
    for (int o = 128; o; o >>= 1) {
        if (threadIdx.x < o) red[threadIdx.x] += red[threadIdx.x + o];
        __syncthreads();
    }
    float nrm = red[0];
    for (int d = threadIdx.x; d < DD; d += 256)
        g_anorm[r * DD + d] = row[d] / nrm;
}

__global__ void rowsumX_kernel() {
    int w = (blockIdx.x * blockDim.x + threadIdx.x) >> 5;
    int lane = threadIdx.x & 31;
    if (w >= AD) return;
    float s = 0.f;
    for (int k = lane; k < AD; k += 32) s += g_X[w * AD + k];
#pragma unroll
    for (int o = 16; o; o >>= 1) s += __shfl_xor_sync(0xffffffffu, s, o);
    if (!lane) g_rsx[w] = s;
}

// permute X into mma fragment order: [m_tile 64][k_tile 128][lane 32][a0..a3]
__global__ void xperm_kernel() {
    int idx = blockIdx.x * 256 + threadIdx.x;       // 0..262143
    int L = idx & 31, kt = (idx >> 5) & 127, mt = idx >> 12;
    int r = mt * 16 + (L >> 2), c = kt * 8 + (L & 3);
    float4 v;
    v.x = tf32_rna(g_X[r * AD + c]);
    v.y = tf32_rna(g_X[(r + 8) * AD + c]);
    v.z = tf32_rna(g_X[r * AD + c + 4]);
    v.w = tf32_rna(g_X[(r + 8) * AD + c + 4]);
    *reinterpret_cast<float4*>(g_Xp + (size_t)idx * 4) = v;
}

__global__ void init_kernel() {
    size_t i4 = ((size_t)blockIdx.x * 256 + threadIdx.x) * 4;
    int a = (int)(i4 / BD);
    float rs = g_rsx[a] * (1.0f / AD);
    float4 q4 = *reinterpret_cast<const float4*>(g_q + i4);
    float4 g;
    g.x = rs - q4.x; g.y = rs - q4.y; g.z = rs - q4.z; g.w = rs - q4.w;
    *reinterpret_cast<float4*>(g_grad + i4) = g;
    float4 cc = make_float4(1.0f / AD, 1.0f / AD, 1.0f / AD, 1.0f / AD);
    *reinterpret_cast<float4*>(g_c + i4) = cc;
}

// =====================================================================
// fp32 SIMT GEMM (X, q, recon)
// =====================================================================
template <bool AKM, bool BKM, int SCALE>
__global__ void __launch_bounds__(256) gemm_kernel(
    const float* __restrict__ A, const float* __restrict__ B, float* __restrict__ C,
    int M, int N, int K, int lda, int ldb, int ldc, const float* __restrict__ scale)
{
    __shared__ float As[16][132];
    __shared__ float Bs[16][132];
    const int tid = threadIdx.x;
    const int tx = tid & 15, ty = tid >> 4;
    const int m0 = blockIdx.y * 128, n0 = blockIdx.x * 128;
    float acc[8][8];
#pragma unroll
    for (int i = 0; i < 8; i++)
#pragma unroll
        for (int j = 0; j < 8; j++) acc[i][j] = 0.f;

    for (int k0 = 0; k0 < K; k0 += 16) {
#pragma unroll
        for (int i = 0; i < 2; i++) {
            int lin = tid + i * 256;
            if (AKM) {
                int kk = lin >> 5, mm = (lin & 31) << 2;
                float4 v = *reinterpret_cast<const float4*>(A + (size_t)(k0 + kk) * lda + (m0 + mm));
                *reinterpret_cast<float4*>(&As[kk][mm]) = v;
            } else {
                int mm = lin >> 2, kk = (lin & 3) << 2;
                float4 v = *reinterpret_cast<const float4*>(A + (size_t)(m0 + mm) * lda + (k0 + kk));
                As[kk + 0][mm] = v.x; As[kk + 1][mm] = v.y;
                As[kk + 2][mm] = v.z; As[kk + 3][mm] = v.w;
            }
        }
#pragma unroll
        for (int i = 0; i < 2; i++) {
            int lin = tid + i * 256;
            if (BKM) {
                int kk = lin >> 5, nn = (lin & 31) << 2;
                float4 v = *reinterpret_cast<const float4*>(B + (size_t)(k0 + kk) * ldb + (n0 + nn));
                *reinterpret_cast<float4*>(&Bs[kk][nn]) = v;
            } else {
                int nn = lin >> 2, kk = (lin & 3) << 2;
                float4 v = *reinterpret_cast<const float4*>(B + (size_t)(n0 + nn) * ldb + (k0 + kk));
                Bs[kk + 0][nn] = v.x; Bs[kk + 1][nn] = v.y;
                Bs[kk + 2][nn] = v.z; Bs[kk + 3][nn] = v.w;
            }
        }
        __syncthreads();
#pragma unroll
        for (int k = 0; k < 16; k++) {
            float af[8], bf[8];
            *reinterpret_cast<float4*>(&af[0]) = *reinterpret_cast<float4*>(&As[k][ty * 8]);
            *reinterpret_cast<float4*>(&af[4]) = *reinterpret_cast<float4*>(&As[k][ty * 8 + 4]);
            *reinterpret_cast<float4*>(&bf[0]) = *reinterpret_cast<float4*>(&Bs[k][tx * 8]);
            *reinterpret_cast<float4*>(&bf[4]) = *reinterpret_cast<float4*>(&Bs[k][tx * 8 + 4]);
#pragma unroll
            for (int i = 0; i < 8; i++)
#pragma unroll
                for (int j = 0; j < 8; j++) acc[i][j] += af[i] * bf[j];
        }
        __syncthreads();
    }
#pragma unroll
    for (int i = 0; i < 8; i++) {
        int m = m0 + ty * 8 + i;
        float rowf = (SCALE == 2) ? scale[m] : 1.f;
#pragma unroll
        for (int j = 0; j < 8; j++) {
            float f = (SCALE == 1) ? scale[n0 + tx * 8 + j] : rowf;
            C[(size_t)m * ldc + n0 + tx * 8 + j] = acc[i][j] * f;
        }
    }
}

// =====================================================================
// xsm = X @ sm via raw mma.sync tf32, fragment-order operands.
// CTA tile 128m x 128n, K chunks of 32 (4 k_tiles), double-buffered.
// 8 warps: warp tile 32m x 64n = 2 x 8 m16n8 tiles.
// smem per buffer: A 16KB + B 16KB.
// =====================================================================
#define A_CH 16384
#define B_CH 16384
#define SMEM_DYN (2 * (A_CH + B_CH))

__global__ void __launch_bounds__(256, 2) xsm_mma_kernel() {
    extern __shared__ char smc[];
    const uint32_t sb = smem_u32(smc);
    const int tid = threadIdx.x;
    const int wid = tid >> 5, lane = tid & 31;
    const int m0 = blockIdx.y * 128, n0 = blockIdx.x * 128;
    const int mt0 = m0 >> 4;         // 8 m_tiles per CTA
    const int nt0 = n0 >> 3;         // 16 n_tiles per CTA

    float acc[2][8][4];
#pragma unroll
    for (int i = 0; i < 2; i++)
#pragma unroll
        for (int j = 0; j < 8; j++)
#pragma unroll
            for (int v = 0; v < 4; v++) acc[i][j][v] = 0.f;

    // cp.async staging: A per m_tile block = 4 k_tiles * 512B = 2KB contig;
    //                   B per n_tile block = 4 k_tiles * 256B = 1KB contig.
#define PREFETCH(CK, BUF) do { \
    const int _kt0 = (CK) * 4; \
    _Pragma("unroll") \
    for (int s = 0; s < 4; s++) { \
        int idx = tid + s * 256;                 /* 0..1023 */ \
        int mtl = idx >> 7, remA = idx & 127; \
        const float* srcA = g_Xp + (((size_t)(mt0 + mtl) * 128 + _kt0) * 32) * 4 + remA * 4; \
        CP16(sb + (BUF) * (A_CH + B_CH) + (mtl * 128 + remA) * 16, srcA); \
        int ntl = idx >> 6, remB = idx & 63; \
        const float* srcB = g_smTp + (((size_t)(nt0 + ntl) * 128 + _kt0) * 32) * 2 + remB * 4; \
        CP16(sb + (BUF) * (A_CH + B_CH) + A_CH + (ntl * 64 + remB) * 16, srcB); \
    } \
    CP_COMMIT(); } while (0)

    PREFETCH(0, 0);

    const int wm = (wid >> 1) * 2;   // first m_tile (local) of this warp
    const int wn = (wid & 1) * 8;    // first n_tile (local) of this warp

    const int NCK = AD / 32;
    for (int ck = 0; ck < NCK; ck++) {
        const int buf = ck & 1;
        if (ck + 1 < NCK) {
            PREFETCH(ck + 1, (ck + 1) & 1);
            CP_WAIT(1);
        } else {
            CP_WAIT(0);
        }
        __syncthreads();

        const char* Abase = smc + buf * (A_CH + B_CH);
        const char* Bbase = Abase + A_CH;

#pragma unroll
        for (int ktl = 0; ktl < 4; ktl++) {
            uint32_t afr[2][4];
#pragma unroll
            for (int i = 0; i < 2; i++) {
                uint4 v = *reinterpret_cast<const uint4*>(
                    Abase + (((wm + i) * 4 + ktl) * 32 + lane) * 16);
                afr[i][0] = v.x; afr[i][1] = v.y; afr[i][2] = v.z; afr[i][3] = v.w;
            }
            uint32_t bfr[8][2];
#pragma unroll
            for (int j = 0; j < 8; j++) {
                uint2 v = *reinterpret_cast<const uint2*>(
                    Bbase + (((wn + j) * 4 + ktl) * 32 + lane) * 8);
                bfr[j][0] = v.x; bfr[j][1] = v.y;
            }
#pragma unroll
            for (int i = 0; i < 2; i++)
#pragma unroll
                for (int j = 0; j < 8; j++)
                    mma_tf32_16n8k8(acc[i][j], afr[i], bfr[j]);
        }
        __syncthreads();
    }
#undef PREFETCH

    // epilogue: c0,c1 at (row, col..col+1); c2,c3 at (row+8, ...)
    const int grp = lane >> 2, q4 = lane & 3;
#pragma unroll
    for (int i = 0; i < 2; i++) {
        int row = m0 + (wid >> 1) * 32 + i * 16 + grp;
#pragma unroll
        for (int j = 0; j < 8; j++) {
            int col = n0 + (wid & 1) * 64 + j * 8 + q4 * 2;
            *reinterpret_cast<float2*>(g_xsm + (size_t)row * BD + col) =
                make_float2(acc[i][j][0], acc[i][j][1]);
            *reinterpret_cast<float2*>(g_xsm + (size_t)(row + 8) * BD + col) =
                make_float2(acc[i][j][2], acc[i][j][3]);
        }
    }
}

// =====================================================================
// full argmin (step 0 only)
// =====================================================================
__global__ void __launch_bounds__(256) argmin_full_kernel() {
    const int a = blockIdx.x;
    const float* row = g_grad + (size_t)a * BD;
    unsigned long long best = ~0ull;
    for (int it = 0; it < 16; it++) {
        int j = threadIdx.x * 4 + it * 1024;
        float4 v = *reinterpret_cast<const float4*>(row + j);
        unsigned long long k0 = packmin(v.x, j);
        unsigned long long k1 = packmin(v.y, j + 1);
        unsigned long long k2 = packmin(v.z, j + 2);
        unsigned long long k3 = packmin(v.w, j + 3);
        if (k1 < k0) k0 = k1;
        if (k3 < k2) k2 = k3;
        if (k2 < k0) k0 = k2;
        if (k0 < best) best = k0;
    }
    __shared__ unsigned long long sk[256];
    sk[threadIdx.x] = best;
    __syncthreads();
    for (int o = 128; o; o >>= 1) {
        if (threadIdx.x < o && sk[threadIdx.x + o] < sk[threadIdx.x])
            sk[threadIdx.x] = sk[threadIdx.x + o];
        __syncthreads();
    }
    if (!threadIdx.x) g_amin[a] = (int)(sk[0] & 0xFFFFFFFFu);
}

__global__ void __launch_bounds__(256) argmin_parts_kernel() {
    const int wid = threadIdx.x >> 5, lane = threadIdx.x & 31;
    const int a = blockIdx.x * 8 + wid;
    unsigned long long best = ~0ull;
#pragma unroll
    for (int k = 0; k < NBLK / 32; k++) {
        unsigned long long v = g_minp[(size_t)a * NBLK + lane + k * 32];
        if (v < best) best = v;
    }
#pragma unroll
    for (int o = 16; o; o >>= 1) {
        unsigned long long v = __shfl_down_sync(0xffffffffu, best, o);
        if (v < best) best = v;
    }
    if (!lane) g_amin[a] = (int)(best & 0xFFFFFFFFu);
}

// =====================================================================
// selection list
// =====================================================================
__device__ __forceinline__ void build_sel_list(
    const int* amin_s, int j0, int* sel_a, int* sel_j, int* nsel_s,
    int tid)
{
    if (tid < 32) {
        int cnt = 0;
        for (int base = 0; base < AD; base += 32) {
            int a = base + tid;
            int jm = amin_s[a];
            bool mt = (jm >= j0 && jm < j0 + 64);
            unsigned mask = __ballot_sync(0xffffffffu, mt);
            if (mt) {
                int p = cnt + __popc(mask & ((1u << tid) - 1u));
                sel_a[p] = a; sel_j[p] = jm;
            }
            cnt += __popc(mask);
        }
        if (tid == 0) *nsel_s = cnt;
    }
}

// =====================================================================
// nondiff step kernels (vectorized, from R8)
// =====================================================================
__global__ void __launch_bounds__(256) nd_reduce_kernel() {
    const int tid = threadIdx.x, tx = tid & 15, ty = tid >> 4;
    const int j0 = blockIdx.x * 64, jb = j0 + tx * 4;
    __shared__ int amin_s[AD];
    __shared__ int sel_a[AD], sel_j[AD], nsel_s;
    for (int a = tid; a < AD; a += 256) amin_s[a] = g_amin[a];
    __syncthreads();
    build_sel_list(amin_s, j0, sel_a, sel_j, &nsel_s, tid);
    __syncthreads();
    const int ns = nsel_s;

    float4 num4 = {0, 0, 0, 0}, den4 = {0, 0, 0, 0};
    for (int a = ty; a < AD; a += 16) {
        size_t idx = (size_t)a * BD + jb;
        float4 cc = *reinterpret_cast<const float4*>(g_c + idx);
        float4 gg = *reinterpret_cast<const float4*>(g_grad + idx);
        float4 qq = *reinterpret_cast<const float4*>(g_q + idx);
        float4 S = {0, 0, 0, 0};
        for (int e = 0; e < ns; e++) {
            float xv = g_X[a * AD + sel_a[e]];
            int d = sel_j[e] - jb;
            S.x += (d == 0) ? xv : 0.f;
            S.y += (d == 1) ? xv : 0.f;
            S.z += (d == 2) ? xv : 0.f;
            S.w += (d == 3) ? xv : 0.f;
        }
        int am = amin_s[a];
        float4 dd, xd;
        dd.x = ((am == jb + 0) ? 1.f : 0.f) - cc.x;
        dd.y = ((am == jb + 1) ? 1.f : 0.f) - cc.y;
        dd.z = ((am == jb + 2) ? 1.f : 0.f) - cc.z;
        dd.w = ((am == jb + 3) ? 1.f : 0.f) - cc.w;
        xd.x = S.x - gg.x - qq.x; xd.y = S.y - gg.y - qq.y;
        xd.z = S.z - gg.z - qq.z; xd.w = S.w - gg.w - qq.w;
        num4.x += dd.x * gg.x; num4.y += dd.y * gg.y;
        num4.z += dd.z * gg.z; num4.w += dd.w * gg.w;
        den4.x += dd.x * xd.x; den4.y += dd.y * xd.y;
        den4.z += dd.z * xd.z; den4.w += dd.w * xd.w;
    }
    __shared__ float4 rn[16][17], rd[16][17];
    __shared__ float colden[16];
    rn[ty][tx] = num4; rd[ty][tx] = den4;
    __syncthreads();
    if (ty == 0) {
        float4 n = rn[0][tx], d = rd[0][tx];
        for (int t = 1; t < 16; t++) {
            float4 n2 = rn[t][tx], d2 = rd[t][tx];
            n.x += n2.x; n.y += n2.y; n.z += n2.z; n.w += n2.w;
            d.x += d2.x; d.y += d2.y; d.z += d2.z; d.w += d2.w;
        }
        *reinterpret_cast<float4*>(g_num + jb) = n;
        colden[tx] = d.x + d.y + d.z + d.w;
    }
    __syncthreads();
    if (tid == 0) {
        float s = 0.f;
        for (int t = 0; t < 16; t++) s += colden[t];
        g_denpart[blockIdx.x] = s;
    }
}

__global__ void __launch_bounds__(256) nd_update_kernel() {
    const int tid = threadIdx.x, tx = tid & 15, ty = tid >> 4;
    const int j0 = blockIdx.x * 64, jb = j0 + tx * 4;
    __shared__ float red[256];
    __shared__ int amin_s[AD];
    __shared__ int sel_a[AD], sel_j[AD], nsel_s;
    red[tid] = g_denpart[tid];
    for (int a = tid; a < AD; a += 256) amin_s[a] = g_amin[a];
    __syncthreads();
    for (int o = 128; o; o >>= 1) {
        if (tid < o) red[tid] += red[tid + o];
        __syncthreads();
    }
    build_sel_list(amin_s, j0, sel_a, sel_j, &nsel_s, tid);
    __syncthreads();
    const int ns = nsel_s;
    const float denom = red[0] + EPSC;
    float4 nm = *reinterpret_cast<const float4*>(g_num + jb);
    float4 lam;
    lam.x = fminf(fmaxf(-nm.x / denom, 0.f), 1.f);
    lam.y = fminf(fmaxf(-nm.y / denom, 0.f), 1.f);
    lam.z = fminf(fmaxf(-nm.z / denom, 0.f), 1.f);
    lam.w = fminf(fmaxf(-nm.w / denom, 0.f), 1.f);

    for (int a = ty; a < AD; a += 16) {
        size_t idx = (size_t)a * BD + jb;
        float4 cc = *reinterpret_cast<const float4*>(g_c + idx);
        float4 gg = *reinterpret_cast<const float4*>(g_grad + idx);
        float4 qq = *reinterpret_cast<const float4*>(g_q + idx);
        float4 S = {0, 0, 0, 0};
        for (int e = 0; e < ns; e++) {
            float xv = g_X[a * AD + sel_a[e]];
            int d = sel_j[e] - jb;
            S.x += (d == 0) ? xv : 0.f;
            S.y += (d == 1) ? xv : 0.f;
            S.z += (d == 2) ? xv : 0.f;
            S.w += (d == 3) ? xv : 0.f;
        }
        int am = amin_s[a];
        float4 dd, xd, c2, g2;
        dd.x = ((am == jb + 0) ? 1.f : 0.f) - cc.x;
        dd.y = ((am == jb + 1) ? 1.f : 0.f) - cc.y;
        dd.z = ((am == jb + 2) ? 1.f : 0.f) - cc.z;
        dd.w = ((am == jb + 3) ? 1.f : 0.f) - cc.w;
        xd.x = S.x - gg.x - qq.x; xd.y = S.y - gg.y - qq.y;
        xd.z = S.z - gg.z - qq.z; xd.w = S.w - gg.w - qq.w;
        c2.x = cc.x + lam.x * dd.x; c2.y = cc.y + lam.y * dd.y;
        c2.z = cc.z + lam.z * dd.z; c2.w = cc.w + lam.w * dd.w;
        g2.x = gg.x + lam.x * xd.x; g2.y = gg.y + lam.y * xd.y;
        g2.z = gg.z + lam.z * xd.z; g2.w = gg.w + lam.w * xd.w;
        *reinterpret_cast<float4*>(g_c + idx)    = c2;
        *reinterpret_cast<float4*>(g_grad + idx) = g2;

        unsigned long long best = packmin(g2.x, jb);
        unsigned long long k1 = packmin(g2.y, jb + 1);
        unsigned long long k2 = packmin(g2.z, jb + 2);
        unsigned long long k3 = packmin(g2.w, jb + 3);
        if (k1 < best) best = k1;
        if (k2 < best) best = k2;
        if (k3 < best) best = k3;
#pragma unroll
        for (int o = 8; o; o >>= 1) {
            unsigned long long v = __shfl_down_sync(0xffffffffu, best, o, 16);
            if (v < best) best = v;
        }
        if (tx == 0) g_minp[(size_t)a * NBLK + blockIdx.x] = best;
    }
}

// =====================================================================
// softmax (vectorized) + fragment-order tf32 B operand writer
// =====================================================================
__global__ void __launch_bounds__(256) softmaxT_kernel() {
    const int tid = threadIdx.x, tx = tid & 15, ty = tid >> 4;
    const int j0 = blockIdx.x * 64, jb = j0 + tx * 4;

    float4 m4 = {-INFINITY, -INFINITY, -INFINITY, -INFINITY};
    float4 s4 = {0, 0, 0, 0};
    for (int a = ty; a < AD; a += 16) {
        float4 g = *reinterpret_cast<const float4*>(g_grad + (size_t)a * BD + jb);
        float v;
        v = -TEMPC * g.x; if (v > m4.x) { s4.x = s4.x * expf(m4.x - v) + 1.f; m4.x = v; } else s4.x += expf(v - m4.x);
        v = -TEMPC * g.y; if (v > m4.y) { s4.y = s4.y * expf(m4.y - v) + 1.f; m4.y = v; } else s4.y += expf(v - m4.y);
        v = -TEMPC * g.z; if (v > m4.z) { s4.z = s4.z * expf(m4.z - v) + 1.f; m4.z = v; } else s4.z += expf(v - m4.z);
        v = -TEMPC * g.w; if (v > m4.w) { s4.w = s4.w * expf(m4.w - v) + 1.f; m4.w = v; } else s4.w += expf(v - m4.w);
    }
    __shared__ float4 mm[16][17], ss[16][17];
    __shared__ float4 fm[16], fsinv[16];
    mm[ty][tx] = m4; ss[ty][tx] = s4;
    __syncthreads();
    if (ty == 0) {
        float4 M = mm[0][tx], S = ss[0][tx];
        for (int t = 1; t < 16; t++) {
            float4 m2 = mm[t][tx], s2 = ss[t][tx];
            float Mn;
            Mn = fmaxf(M.x, m2.x); S.x = S.x * expf(M.x - Mn) + s2.x * expf(m2.x - Mn); M.x = Mn;
            Mn = fmaxf(M.y, m2.y); S.y = S.y * expf(M.y - Mn) + s2.y * expf(m2.y - Mn); M.y = Mn;
            Mn = fmaxf(M.z, m2.z); S.z = S.z * expf(M.z - Mn) + s2.z * expf(m2.z - Mn); M.z = Mn;
            Mn = fmaxf(M.w, m2.w); S.w = S.w * expf(M.w - Mn) + s2.w * expf(m2.w - Mn); M.w = Mn;
        }
        fm[tx] = M;
        fsinv[tx] = make_float4(1.f / S.x, 1.f / S.y, 1.f / S.z, 1.f / S.w);
    }
    __syncthreads();
    const float4 M4 = fm[tx];
    const float4 I4 = fsinv[tx];

    __shared__ float tile[32][68];
    const int L = tid & 31, nt = tid >> 5;   // nt: 8 n_tiles per 64-col block
    for (int at = 0; at < 32; at++) {
        const int a0 = at * 32;
#pragma unroll
        for (int half = 0; half < 2; half++) {
            int aa = ty + half * 16;
            size_t idx = (size_t)(a0 + aa) * BD + jb;
            float4 g = *reinterpret_cast<const float4*>(g_grad + idx);
            float4 e;
            e.x = expf(-TEMPC * g.x - M4.x) * I4.x;
            e.y = expf(-TEMPC * g.y - M4.y) * I4.y;
            e.z = expf(-TEMPC * g.z - M4.z) * I4.z;
            e.w = expf(-TEMPC * g.w - M4.w) * I4.w;
            *reinterpret_cast<float4*>(g_sm + idx) = e;
            tile[aa][tx * 4 + 0] = e.x;
            tile[aa][tx * 4 + 1] = e.y;
            tile[aa][tx * 4 + 2] = e.z;
            tile[aa][tx * 4 + 3] = e.w;
        }
        __syncthreads();
        // fragment-order write: b0 = (k = kt*8 + L%4, n), b1 = (k + 4, n)
#pragma unroll
        for (int kt = 0; kt < 4; kt++) {
            float v0 = tile[kt * 8 + (L & 3)][nt * 8 + (L >> 2)];
            float v1 = tile[kt * 8 + (L & 3) + 4][nt * 8 + (L >> 2)];
            size_t o = (((size_t)(j0 / 8 + nt) * 128 + (at * 4 + kt)) * 32 + L) * 2;
            *reinterpret_cast<float2*>(g_smTp + o) =
                make_float2(tf32_rna(v0), tf32_rna(v1));
        }
        __syncthreads();
    }
}

// =====================================================================
// diff step reduce / update (vectorized, from R8)
// =====================================================================
__global__ void __launch_bounds__(256) d_reduce_kernel() {
    const int tid = threadIdx.x, tx = tid & 15, ty = tid >> 4;
    const int jb = blockIdx.x * 64 + tx * 4;
    float4 num4 = {0, 0, 0, 0}, den4 = {0, 0, 0, 0};
    for (int a = ty; a < AD; a += 16) {
        size_t idx = (size_t)a * BD + jb;
        float4 sm = *reinterpret_cast<const float4*>(g_sm + idx);
        float4 cc = *reinterpret_cast<const float4*>(g_c + idx);
        float4 xs = *reinterpret_cast<const float4*>(g_xsm + idx);
        float4 gg = *reinterpret_cast<const float4*>(g_grad + idx);
        float4 qq = *reinterpret_cast<const float4*>(g_q + idx);
        float4 dd, xd;
        dd.x = sm.x - cc.x; dd.y = sm.y - cc.y; dd.z = sm.z - cc.z; dd.w = sm.w - cc.w;
        xd.x = xs.x - gg.x - qq.x; xd.y = xs.y - gg.y - qq.y;
        xd.z = xs.z - gg.z - qq.z; xd.w = xs.w - gg.w - qq.w;
        num4.x += dd.x * gg.x; num4.y += dd.y * gg.y;
        num4.z += dd.z * gg.z; num4.w += dd.w * gg.w;
        den4.x += dd.x * xd.x; den4.y += dd.y * xd.y;
        den4.z += dd.z * xd.z; den4.w += dd.w * xd.w;
    }
    __shared__ float4 rn[16][17], rd[16][17];
    __shared__ float colden[16];
    rn[ty][tx] = num4; rd[ty][tx] = den4;
    __syncthreads();
    if (ty == 0) {
        float4 n = rn[0][tx], d = rd[0][tx];
        for (int t = 1; t < 16; t++) {
            float4 n2 = rn[t][tx], d2 = rd[t][tx];
            n.x += n2.x; n.y += n2.y; n.z += n2.z; n.w += n2.w;
            d.x += d2.x; d.y += d2.y; d.z += d2.z; d.w += d2.w;
        }
        *reinterpret_cast<float4*>(g_num + jb) = n;
        colden[tx] = d.x + d.y + d.z + d.w;
    }
    __syncthreads();
    if (tid == 0) {
        float s = 0.f;
        for (int t = 0; t < 16; t++) s += colden[t];
        g_denpart[blockIdx.x] = s;
    }
}

template <bool LAST>
__global__ void __launch_bounds__(256) d_update_kernel() {
    const int tid = threadIdx.x, tx = tid & 15, ty = tid >> 4;
    const int jb = blockIdx.x * 64 + tx * 4;
    __shared__ float red[256];
    red[tid] = g_denpart[tid];
    __syncthreads();
    for (int o = 128; o; o >>= 1) {
        if (tid < o) red[tid] += red[tid + o];
        __syncthreads();
    }
    const float denom = red[0] + EPSC;
    float4 nm = *reinterpret_cast<const float4*>(g_num + jb);
    float4 lam;
    lam.x = fminf(fmaxf(-nm.x / denom, 0.f), 1.f);
    lam.y = fminf(fmaxf(-nm.y / denom, 0.f), 1.f);
    lam.z = fminf(fmaxf(-nm.z / denom, 0.f), 1.f);
    lam.w = fminf(fmaxf(-nm.w / denom, 0.f), 1.f);
    for (int a = ty; a < AD; a += 16) {
        size_t idx = (size_t)a * BD + jb;
        float4 sm = *reinterpret_cast<const float4*>(g_sm + idx);
        float4 cc = *reinterpret_cast<const float4*>(g_c + idx);
        float4 c2;
        c2.x = cc.x + lam.x * (sm.x - cc.x);
        c2.y = cc.y + lam.y * (sm.y - cc.y);
        c2.z = cc.z + lam.z * (sm.z - cc.z);
        c2.w = cc.w + lam.w * (sm.w - cc.w);
        *reinterpret_cast<float4*>(g_c + idx) = c2;
        if (!LAST) {
            float4 xs = *reinterpret_cast<const float4*>(g_xsm + idx);
            float4 gg = *reinterpret_cast<const float4*>(g_grad + idx);
            float4 qq = *reinterpret_cast<const float4*>(g_q + idx);
            float4 g2;
            g2.x = gg.x + lam.x * (xs.x - gg.x - qq.x);
            g2.y = gg.y + lam.y * (xs.y - gg.y - qq.y);
            g2.z = gg.z + lam.z * (xs.z - gg.z - qq.z);
            g2.w = gg.w + lam.w * (xs.w - gg.w - qq.w);
            *reinterpret_cast<float4*>(g_grad + idx) = g2;
        }
    }
}

// =====================================================================
// host launcher
// =====================================================================
extern "C" void kernel_launch(void* const* d_in, const int* in_sizes, int n_in,
                              void* d_out, int out_size)
{
    const float* y     = (const float*)d_in[0];
    const float* atoms = (const float*)d_in[1];
    float* out = (float*)d_out;

    float *p_anorm, *p_X, *p_q, *p_c, *p_invyn, *p_ynorm;
    cudaGetSymbolAddress((void**)&p_anorm, g_anorm);
    cudaGetSymbolAddress((void**)&p_X,     g_X);
    cudaGetSymbolAddress((void**)&p_q,     g_q);
    cudaGetSymbolAddress((void**)&p_c,     g_c);
    cudaGetSymbolAddress((void**)&p_invyn, g_invyn);
    cudaGetSymbolAddress((void**)&p_ynorm, g_ynorm);

    cudaFuncSetAttribute(xsm_mma_kernel,
                         cudaFuncAttributeMaxDynamicSharedMemorySize, SMEM_DYN);

    ynorm_kernel<<<BD / 8, 256>>>(y);
    anorm_kernel<<<AD, 256>>>(atoms);

    gemm_kernel<false, false, 0><<<dim3(AD / 128, AD / 128), 256>>>(
        p_anorm, p_anorm, p_X, AD, AD, DD, DD, DD, AD, nullptr);
    rowsumX_kernel<<<AD / 8, 256>>>();
    xperm_kernel<<<1024, 256>>>();

    gemm_kernel<false, false, 1><<<dim3(BD / 128, AD / 128), 256>>>(
        p_anorm, y, p_q, AD, BD, DD, DD, DD, BD, p_invyn);

    init_kernel<<<(AD * BD) / 1024, 256>>>();

    argmin_full_kernel<<<AD, 256>>>();
    for (int s = 0; s < NONDIFF; s++) {
        nd_reduce_kernel<<<NBLK, 256>>>();
        nd_update_kernel<<<NBLK, 256>>>();
        if (s + 1 < NONDIFF) argmin_parts_kernel<<<AD / 8, 256>>>();
    }

    for (int s = 0; s < DIFFST; s++) {
        softmaxT_kernel<<<NBLK, 256>>>();
        xsm_mma_kernel<<<dim3(BD / 128, AD / 128), 256, SMEM_DYN>>>();
        d_reduce_kernel<<<NBLK, 256>>>();
        if (s + 1 < DIFFST) d_update_kernel<false><<<NBLK, 256>>>();
        else                d_update_kernel<true ><<<NBLK, 256>>>();
    }

    gemm_kernel<true, true, 2><<<dim3(DD / 128, BD / 128), 256>>>(
        p_c, p_anorm, out, BD, DD, AD, BD, DD, DD, p_ynorm);
}